// round 2
// baseline (speedup 1.0000x reference)
#include <cuda_runtime.h>
#include <cstdint>
#include <math.h>

// ---------------------------------------------------------------------------
// MoE layer: B=4,S=2048,D=1024,H=4096,E=8,topK=2, T=8192 tokens.
// Sparse dispatch: only top-2 experts per token are computed.
// ---------------------------------------------------------------------------

#define D_DIM 1024
#define H_DIM 4096
#define NE    8
#define MAXT  8192
#define MAXSLOT (MAXT * 2)
#define MAXRBLK (MAXT / 8)   // router blocks (8 tokens per block)

// ------------------------- device scratch (globals) ------------------------
__device__ float g_partp[MAXRBLK * NE];   // per-block partial prob sums
__device__ int   g_partc[MAXRBLK * NE];   // per-block partial expert counts
__device__ float g_psum[NE];
__device__ int   g_cnt[NE];
__device__ int   g_off[NE + 1];
__device__ int   g_cur[NE];
__device__ int   g_idx2[MAXT * 2];        // top-2 expert ids per token
__device__ float g_w2[MAXT * 2];          // normalized top-2 weights
__device__ int   g_slot[MAXT * 2];        // slot index per (token,k)
__device__ int   g_tok[MAXSLOT];          // token id per slot
__device__ float g_Hbuf[(size_t)MAXSLOT * H_DIM];  // 256 MB
__device__ float g_Ybuf[(size_t)MAXSLOT * D_DIM];  // 64 MB

// ------------------------------- helpers -----------------------------------
__device__ __forceinline__ float gelu_f(float v) {
    return 0.5f * v * (1.0f + erff(v * 0.7071067811865476f));
}

__device__ __forceinline__ uint64_t pack_dup(float a) {
    uint64_t r;
    asm("mov.b64 %0, {%1, %1};" : "=l"(r) : "r"(__float_as_uint(a)));
    return r;
}

__device__ __forceinline__ void ffma2(uint64_t& acc, uint64_t a, uint64_t b) {
    asm("fma.rn.f32x2 %0, %1, %2, %0;" : "+l"(acc) : "l"(a), "l"(b));
}

// ------------------------------- router ------------------------------------
// 256 threads = 8 warps, 1 token per warp. Deterministic block-level reduce
// (fixed order, no float atomics) for the aux-loss statistics.
__global__ __launch_bounds__(256) void router_kernel(
    const float* __restrict__ x, const float* __restrict__ Wg, int T)
{
    __shared__ float sp[8][NE];
    __shared__ int   si[8][2];

    int tid  = threadIdx.x;
    int warp = tid >> 5;
    int lane = tid & 31;
    int t = blockIdx.x * 8 + warp;

    float acc[NE];
#pragma unroll
    for (int e = 0; e < NE; e++) acc[e] = 0.f;

    if (t < T) {
        const float* xr = x + (size_t)t * D_DIM;
        for (int d = lane; d < D_DIM; d += 32) {
            float xv = xr[d];
            const float* wr = Wg + d * NE;
#pragma unroll
            for (int e = 0; e < NE; e++) acc[e] += xv * wr[e];
        }
    }
#pragma unroll
    for (int e = 0; e < NE; e++) {
#pragma unroll
        for (int o = 16; o > 0; o >>= 1)
            acc[e] += __shfl_xor_sync(0xFFFFFFFFu, acc[e], o);
    }

    if (lane == 0) {
        if (t < T) {
            float m = acc[0];
#pragma unroll
            for (int e = 1; e < NE; e++) m = fmaxf(m, acc[e]);
            float p[NE];
            float s = 0.f;
#pragma unroll
            for (int e = 0; e < NE; e++) { p[e] = expf(acc[e] - m); s += p[e]; }
            float inv = 1.0f / s;
#pragma unroll
            for (int e = 0; e < NE; e++) p[e] *= inv;

            // top-2, first-occurrence tie-break (matches jax.lax.top_k)
            int i0 = 0;
#pragma unroll
            for (int e = 1; e < NE; e++) if (p[e] > p[i0]) i0 = e;
            int i1 = (i0 == 0) ? 1 : 0;
#pragma unroll
            for (int e = 0; e < NE; e++)
                if (e != i0 && p[e] > p[i1] && e < i1) i1 = e;  // placeholder, fixed below
            // redo i1 properly (first index among e!=i0 with max p)
            i1 = -1;
#pragma unroll
            for (int e = 0; e < NE; e++) {
                if (e == i0) continue;
                if (i1 < 0 || p[e] > p[i1]) i1 = e;
            }

            float ws = p[i0] + p[i1];
            g_idx2[2 * t]     = i0;
            g_idx2[2 * t + 1] = i1;
            g_w2[2 * t]       = p[i0] / ws;
            g_w2[2 * t + 1]   = p[i1] / ws;
#pragma unroll
            for (int e = 0; e < NE; e++) sp[warp][e] = p[e];
            si[warp][0] = i0; si[warp][1] = i1;
        } else {
#pragma unroll
            for (int e = 0; e < NE; e++) sp[warp][e] = 0.f;
            si[warp][0] = -1; si[warp][1] = -1;
        }
    }
    __syncthreads();
    if (tid < NE) {
        float s = 0.f; int c = 0;
#pragma unroll
        for (int w = 0; w < 8; w++) {
            s += sp[w][tid];
            if (si[w][0] == tid || si[w][1] == tid) c++;
        }
        g_partp[blockIdx.x * NE + tid] = s;
        g_partc[blockIdx.x * NE + tid] = c;
    }
}

// ------------------------------- reduce ------------------------------------
__global__ void reduce_kernel(int nblk, int T, float* __restrict__ aux_out) {
    int tid = threadIdx.x;
    if (tid < NE) {
        float ps = 0.f; int cs = 0;
        for (int b = 0; b < nblk; b++) {
            ps += g_partp[b * NE + tid];
            cs += g_partc[b * NE + tid];
        }
        g_psum[tid] = ps;
        g_cnt[tid]  = cs;
        g_cur[tid]  = 0;
    }
    __syncthreads();
    if (tid == 0) {
        int off = 0;
        for (int e = 0; e < NE; e++) { g_off[e] = off; off += g_cnt[e]; }
        g_off[NE] = off;
        float invT = 1.0f / (float)T;
        float aux = 0.f;
        for (int e = 0; e < NE; e++)
            aux += ((float)g_cnt[e] * invT) * (g_psum[e] * invT);
        *aux_out = (float)NE * aux;
    }
}

// ------------------------------- scatter -----------------------------------
__global__ void scatter_kernel(int T) {
    int t = blockIdx.x * 256 + threadIdx.x;
    if (t >= T) return;
#pragma unroll
    for (int k = 0; k < 2; k++) {
        int e = g_idx2[2 * t + k];
        int pos = atomicAdd(&g_cur[e], 1);
        int s = g_off[e] + pos;
        g_tok[s] = t;
        g_slot[2 * t + k] = s;
    }
}

// ------------------------------- grouped GEMM -------------------------------
// 128x128x16 tiles, 256 threads, 8x8 thread-tile with N packed as f32x2 pairs
// (fma.rn.f32x2 doubles fp32 FMA throughput on sm_100a).
// FIRST=true : A = gathered x rows (via g_tok), Out = g_Hbuf, GELU epilogue.
// FIRST=false: A = g_Hbuf (slot-contiguous), Out = g_Ybuf, plain epilogue.
template <int KDIM, int NTOT, bool FIRST>
__global__ __launch_bounds__(256) void moe_gemm(
    const float* __restrict__ Aparam,      // x for FIRST, unused otherwise
    const float* __restrict__ W,           // [E, KDIM, NTOT]
    const float* __restrict__ bias)        // [E, NTOT]
{
    constexpr int BM = 128, BN = 128, BK = 16;
    int e = blockIdx.z;
    int seg0 = g_off[e];
    int M = g_off[e + 1] - seg0;
    int rowTile = blockIdx.y * BM;
    if (rowTile >= M) return;
    int colTile = blockIdx.x * BN;

    __shared__ float As[BK][BM];
    __shared__ float Bs[BK][BN];

    int tid = threadIdx.x;
    int ty = tid >> 4;      // 0..15
    int tx = tid & 15;      // 0..15

    const float* Wb = W + (size_t)e * KDIM * NTOT;
    const float* Abase = FIRST ? Aparam : g_Hbuf;
    float* Out = FIRST ? g_Hbuf : g_Ybuf;

    // A load mapping: 2 x float4 per thread
    int a_r = tid >> 2;            // 0..63
    int a_k = (tid & 3) * 4;
    int r0 = rowTile + a_r, r1 = rowTile + a_r + 64;
    bool ok0 = r0 < M, ok1 = r1 < M;
    const float *Arow0, *Arow1;
    if (FIRST) {
        int t0 = ok0 ? g_tok[seg0 + r0] : 0;
        int t1 = ok1 ? g_tok[seg0 + r1] : 0;
        Arow0 = Abase + (size_t)t0 * KDIM;
        Arow1 = Abase + (size_t)t1 * KDIM;
    } else {
        Arow0 = Abase + (size_t)(seg0 + (ok0 ? r0 : 0)) * KDIM;
        Arow1 = Abase + (size_t)(seg0 + (ok1 ? r1 : 0)) * KDIM;
    }
    // B load mapping: 2 x float4 per thread
    int b_r = tid >> 5;            // 0..7
    int b_c = (tid & 31) * 4;

    uint64_t acc[8][4] = {};       // 8 rows x 4 f32x2 col-pairs

    for (int k0 = 0; k0 < KDIM; k0 += BK) {
        float4 av0 = ok0 ? *(const float4*)(Arow0 + k0 + a_k)
                         : make_float4(0.f, 0.f, 0.f, 0.f);
        float4 av1 = ok1 ? *(const float4*)(Arow1 + k0 + a_k)
                         : make_float4(0.f, 0.f, 0.f, 0.f);
        As[a_k + 0][a_r] = av0.x;  As[a_k + 1][a_r] = av0.y;
        As[a_k + 2][a_r] = av0.z;  As[a_k + 3][a_r] = av0.w;
        As[a_k + 0][a_r + 64] = av1.x;  As[a_k + 1][a_r + 64] = av1.y;
        As[a_k + 2][a_r + 64] = av1.z;  As[a_k + 3][a_r + 64] = av1.w;

        float4 bv0 = *(const float4*)(Wb + (size_t)(k0 + b_r) * NTOT + colTile + b_c);
        float4 bv1 = *(const float4*)(Wb + (size_t)(k0 + b_r + 8) * NTOT + colTile + b_c);
        *(float4*)&Bs[b_r][b_c]     = bv0;
        *(float4*)&Bs[b_r + 8][b_c] = bv1;
        __syncthreads();

#pragma unroll
        for (int kk = 0; kk < BK; kk++) {
            uint64_t ap[8];
#pragma unroll
            for (int i = 0; i < 8; i++)
                ap[i] = pack_dup(As[kk][ty * 8 + i]);
            uint64_t bq[4];
#pragma unroll
            for (int j = 0; j < 4; j++)
                bq[j] = *(const uint64_t*)&Bs[kk][tx * 8 + j * 2];
#pragma unroll
            for (int i = 0; i < 8; i++)
#pragma unroll
                for (int j = 0; j < 4; j++)
                    ffma2(acc[i][j], ap[i], bq[j]);
        }
        __syncthreads();
    }

    const float* brow = bias + (size_t)e * NTOT + colTile + tx * 8;
#pragma unroll
    for (int i = 0; i < 8; i++) {
        int r = rowTile + ty * 8 + i;
        if (r < M) {
            float* orow = Out + (size_t)(seg0 + r) * NTOT + colTile + tx * 8;
#pragma unroll
            for (int j = 0; j < 4; j++) {
                union { uint64_t u; float2 f; } cv;
                cv.u = acc[i][j];
                float c0 = cv.f.x + brow[j * 2];
                float c1 = cv.f.y + brow[j * 2 + 1];
                if (FIRST) { c0 = gelu_f(c0); c1 = gelu_f(c1); }
                ((float2*)orow)[j] = make_float2(c0, c1);
            }
        }
    }
}

// ------------------------------- combine -----------------------------------
__global__ __launch_bounds__(256) void combine_kernel(float* __restrict__ out, int T) {
    size_t i = (size_t)blockIdx.x * 256 + threadIdx.x;
    size_t total = (size_t)T * (D_DIM / 4);
    if (i >= total) return;
    int t  = (int)(i >> 8);        // D_DIM/4 == 256
    int d4 = (int)(i & 255);
    float w0 = g_w2[2 * t], w1 = g_w2[2 * t + 1];
    int s0 = g_slot[2 * t], s1 = g_slot[2 * t + 1];
    float4 a = ((const float4*)(g_Ybuf + (size_t)s0 * D_DIM))[d4];
    float4 b = ((const float4*)(g_Ybuf + (size_t)s1 * D_DIM))[d4];
    float4 o;
    o.x = w0 * a.x + w1 * b.x;
    o.y = w0 * a.y + w1 * b.y;
    o.z = w0 * a.z + w1 * b.z;
    o.w = w0 * a.w + w1 * b.w;
    ((float4*)(out + (size_t)t * D_DIM))[d4] = o;
}

// ------------------------------- launch ------------------------------------
extern "C" void kernel_launch(void* const* d_in, const int* in_sizes, int n_in,
                              void* d_out, int out_size)
{
    const float* x  = (const float*)d_in[0];
    const float* Wg = (const float*)d_in[1];
    const float* W1 = (const float*)d_in[2];
    const float* b1 = (const float*)d_in[3];
    const float* W2 = (const float*)d_in[4];
    const float* b2 = (const float*)d_in[5];
    float* out = (float*)d_out;

    int T = in_sizes[0] / D_DIM;
    if (T > MAXT) T = MAXT;

    int nblk = (T + 7) / 8;
    router_kernel<<<nblk, 256>>>(x, Wg, T);
    reduce_kernel<<<1, 32>>>(nblk, T, out + (size_t)T * D_DIM);
    scatter_kernel<<<(T + 255) / 256, 256>>>(T);

    int gy = (T + 127) / 128;   // worst case: one expert takes every token
    moe_gemm<D_DIM, H_DIM, true ><<<dim3(H_DIM / 128, gy, NE), 256>>>(x, W1, b1);
    moe_gemm<H_DIM, D_DIM, false><<<dim3(D_DIM / 128, gy, NE), 256>>>(nullptr, W2, b2);

    combine_kernel<<<(unsigned)(((size_t)T * 256 + 255) / 256), 256>>>(out, T);
}

// round 9
// speedup vs baseline: 2.0921x; 2.0921x over previous
#include <cuda_runtime.h>
#include <cuda_bf16.h>
#include <cstdint>
#include <math.h>

// ---------------------------------------------------------------------------
// MoE: B=4,S=2048,D=1024,H=4096,E=8,top2. T=8192.
// HMMA bf16 split GEMMs (Ah*Bh + Ah*Bl + Al*Bh) with IN-KERNEL fp32->bf16
// hi/lo conversion. Structural envelope matches the R2-passing kernel:
// static smem <= 48KB, no cudaFuncSetAttribute, no cp.async, no lambdas,
// globals ~320MB (H fp32 + Y fp32 only).
// ---------------------------------------------------------------------------

#define D_DIM 1024
#define H_DIM 4096
#define NE    8
#define MAXT  8192
#define MAXSLOT (MAXT * 2)
#define MAXRBLK (MAXT / 8)

__device__ float g_partp[MAXRBLK * NE];
__device__ int   g_partc[MAXRBLK * NE];
__device__ float g_psum[NE];
__device__ int   g_cnt[NE];
__device__ int   g_off[NE + 1];
__device__ int   g_cur[NE];
__device__ int   g_idx2[MAXT * 2];
__device__ float g_w2[MAXT * 2];
__device__ int   g_slot[MAXT * 2];
__device__ int   g_tok[MAXSLOT];
__device__ float g_Hbuf[(size_t)MAXSLOT * H_DIM];  // 256 MB fp32
__device__ float g_Ybuf[(size_t)MAXSLOT * D_DIM];  // 64 MB fp32

// ------------------------------- helpers -----------------------------------
__device__ __forceinline__ uint32_t smem_u32(const void* p) {
    uint32_t a;
    asm("{ .reg .u64 t; cvta.to.shared.u64 t, %1; cvt.u32.u64 %0, t; }"
        : "=r"(a) : "l"(p));
    return a;
}
__device__ __forceinline__ void ldm_x4(uint32_t& r0, uint32_t& r1,
                                       uint32_t& r2, uint32_t& r3, uint32_t addr) {
    asm volatile("ldmatrix.sync.aligned.m8n8.x4.shared.b16 {%0,%1,%2,%3}, [%4];\n"
                 : "=r"(r0), "=r"(r1), "=r"(r2), "=r"(r3) : "r"(addr));
}
__device__ __forceinline__ void ldm_x4_t(uint32_t& r0, uint32_t& r1,
                                         uint32_t& r2, uint32_t& r3, uint32_t addr) {
    asm volatile("ldmatrix.sync.aligned.m8n8.x4.trans.shared.b16 {%0,%1,%2,%3}, [%4];\n"
                 : "=r"(r0), "=r"(r1), "=r"(r2), "=r"(r3) : "r"(addr));
}
__device__ __forceinline__ void mma16816(float& d0, float& d1, float& d2, float& d3,
                                         uint32_t a0, uint32_t a1, uint32_t a2, uint32_t a3,
                                         uint32_t b0, uint32_t b1) {
    asm volatile(
        "mma.sync.aligned.m16n8k16.row.col.f32.bf16.bf16.f32 "
        "{%0,%1,%2,%3}, {%4,%5,%6,%7}, {%8,%9}, {%0,%1,%2,%3};\n"
        : "+f"(d0), "+f"(d1), "+f"(d2), "+f"(d3)
        : "r"(a0), "r"(a1), "r"(a2), "r"(a3), "r"(b0), "r"(b1));
}
__device__ __forceinline__ void sts8(uint32_t addr, uint32_t x, uint32_t y) {
    asm volatile("st.shared.v2.b32 [%0], {%1,%2};\n"
                 :: "r"(addr), "r"(x), "r"(y) : "memory");
}
// A tile: [row][32 bf16] = 64B rows, 4 x 16B chunks, swizzle c^((row>>1)&3)
__device__ __forceinline__ uint32_t a_off(int row, int chunk) {
    return (uint32_t)((row * 4 + (chunk ^ ((row >> 1) & 3))) << 4);
}
// B tile: [k][64 bf16] = 128B rows, 8 x 16B chunks, swizzle c^(k&7)
__device__ __forceinline__ uint32_t b_off(int k, int chunk) {
    return (uint32_t)((k * 8 + (chunk ^ (k & 7))) << 4);
}
__device__ __forceinline__ uint32_t pack_bf2(__nv_bfloat16 a, __nv_bfloat16 b) {
    return (uint32_t)__bfloat16_as_ushort(a) | ((uint32_t)__bfloat16_as_ushort(b) << 16);
}
__device__ __forceinline__ void split_f4(float4 v, uint32_t& h0, uint32_t& h1,
                                         uint32_t& l0, uint32_t& l1) {
    __nv_bfloat16 hx = __float2bfloat16_rn(v.x);
    __nv_bfloat16 hy = __float2bfloat16_rn(v.y);
    __nv_bfloat16 hz = __float2bfloat16_rn(v.z);
    __nv_bfloat16 hw = __float2bfloat16_rn(v.w);
    __nv_bfloat16 lx = __float2bfloat16_rn(v.x - __bfloat162float(hx));
    __nv_bfloat16 ly = __float2bfloat16_rn(v.y - __bfloat162float(hy));
    __nv_bfloat16 lz = __float2bfloat16_rn(v.z - __bfloat162float(hz));
    __nv_bfloat16 lw = __float2bfloat16_rn(v.w - __bfloat162float(hw));
    h0 = pack_bf2(hx, hy); h1 = pack_bf2(hz, hw);
    l0 = pack_bf2(lx, ly); l1 = pack_bf2(lz, lw);
}
__device__ __forceinline__ float gelu_f(float v) {
    return 0.5f * v * (1.0f + erff(v * 0.7071067811865476f));
}

// ------------------------------- router ------------------------------------
__global__ __launch_bounds__(256) void router_kernel(
    const float* __restrict__ x, const float* __restrict__ Wg, int T)
{
    __shared__ float sp[8][NE];
    __shared__ int   si[8][2];
    int tid = threadIdx.x, warp = tid >> 5, lane = tid & 31;
    int t = blockIdx.x * 8 + warp;

    float acc[NE];
#pragma unroll
    for (int e = 0; e < NE; e++) acc[e] = 0.f;
    if (t < T) {
        const float* xr = x + (size_t)t * D_DIM;
        for (int d = lane; d < D_DIM; d += 32) {
            float xv = xr[d];
            const float* wr = Wg + d * NE;
#pragma unroll
            for (int e = 0; e < NE; e++) acc[e] += xv * wr[e];
        }
    }
#pragma unroll
    for (int e = 0; e < NE; e++)
#pragma unroll
        for (int o = 16; o > 0; o >>= 1)
            acc[e] += __shfl_xor_sync(0xFFFFFFFFu, acc[e], o);

    if (lane == 0) {
        if (t < T) {
            float m = acc[0];
#pragma unroll
            for (int e = 1; e < NE; e++) m = fmaxf(m, acc[e]);
            float p[NE]; float s = 0.f;
#pragma unroll
            for (int e = 0; e < NE; e++) { p[e] = expf(acc[e] - m); s += p[e]; }
            float inv = 1.0f / s;
#pragma unroll
            for (int e = 0; e < NE; e++) p[e] *= inv;
            int i0 = 0; float v0 = p[0];
#pragma unroll
            for (int e = 1; e < NE; e++)
                if (p[e] > v0) { v0 = p[e]; i0 = e; }
            int i1 = -1; float v1 = -1.f;
#pragma unroll
            for (int e = 0; e < NE; e++) {
                if (e == i0) continue;
                if (p[e] > v1) { v1 = p[e]; i1 = e; }
            }
            float ws = v0 + v1;
            g_idx2[2 * t] = i0;  g_idx2[2 * t + 1] = i1;
            g_w2[2 * t] = v0 / ws;  g_w2[2 * t + 1] = v1 / ws;
#pragma unroll
            for (int e = 0; e < NE; e++) sp[warp][e] = p[e];
            si[warp][0] = i0; si[warp][1] = i1;
        } else {
#pragma unroll
            for (int e = 0; e < NE; e++) sp[warp][e] = 0.f;
            si[warp][0] = -1; si[warp][1] = -1;
        }
    }
    __syncthreads();
    if (tid < NE) {
        float s = 0.f; int c = 0;
#pragma unroll
        for (int w = 0; w < 8; w++) {
            s += sp[w][tid];
            if (si[w][0] == tid || si[w][1] == tid) c++;
        }
        g_partp[blockIdx.x * NE + tid] = s;
        g_partc[blockIdx.x * NE + tid] = c;
    }
}

__global__ void reduce_kernel(int nblk, int T, float* __restrict__ aux_out) {
    int tid = threadIdx.x;
    if (tid < NE) {
        float ps = 0.f; int cs = 0;
        for (int b = 0; b < nblk; b++) {
            ps += g_partp[b * NE + tid];
            cs += g_partc[b * NE + tid];
        }
        g_psum[tid] = ps; g_cnt[tid] = cs; g_cur[tid] = 0;
    }
    __syncthreads();
    if (tid == 0) {
        int off = 0;
        for (int e = 0; e < NE; e++) { g_off[e] = off; off += g_cnt[e]; }
        g_off[NE] = off;
        float invT = 1.0f / (float)T;
        float aux = 0.f;
        for (int e = 0; e < NE; e++)
            aux += ((float)g_cnt[e] * invT) * (g_psum[e] * invT);
        *aux_out = (float)NE * aux;
    }
}

__global__ void scatter_kernel(int T) {
    int t = blockIdx.x * 256 + threadIdx.x;
    if (t >= T) return;
#pragma unroll
    for (int k = 0; k < 2; k++) {
        int e = g_idx2[2 * t + k];
        int pos = atomicAdd(&g_cur[e], 1);
        int s = g_off[e] + pos;
        g_tok[s] = t;
        g_slot[2 * t + k] = s;
    }
}

// --------------------------- HMMA grouped GEMM -----------------------------
// CTA 128(M) x 64(N), BK=32. 8 warps (4x2), warp tile 32x32.
// Single smem buffer, double-buffered through registers:
//   [sync] store regs(s)->smem(convert hi/lo) [sync] LDG regs(s+1) ; compute(s)
// A fp32 rows gathered via srow; W fp32 native [K][N] -> ldmatrix.trans.
#define LOADG(S_) do { int k0_ = (S_) * 32;                                   \
    ra0 = *(const float4*)(srcA + sr0 + k0_ + af0);                           \
    ra1 = *(const float4*)(srcA + sr1 + k0_ + af1);                           \
    ra2 = *(const float4*)(srcA + sr2 + k0_ + af2);                           \
    ra3 = *(const float4*)(srcA + sr3 + k0_ + af3);                           \
    rb0 = *(const float4*)(pB0 + (size_t)k0_ * NTOT);                         \
    rb1 = *(const float4*)(pB1 + (size_t)k0_ * NTOT);                         \
} while (0)

#define STORES() do {                                                         \
    uint32_t h0_, h1_, l0_, l1_;                                              \
    split_f4(ra0, h0_, h1_, l0_, l1_);                                        \
    sts8(aAh + sao0, h0_, h1_); sts8(aAl + sao0, l0_, l1_);                   \
    split_f4(ra1, h0_, h1_, l0_, l1_);                                        \
    sts8(aAh + sao1, h0_, h1_); sts8(aAl + sao1, l0_, l1_);                   \
    split_f4(ra2, h0_, h1_, l0_, l1_);                                        \
    sts8(aAh + sao2, h0_, h1_); sts8(aAl + sao2, l0_, l1_);                   \
    split_f4(ra3, h0_, h1_, l0_, l1_);                                        \
    sts8(aAh + sao3, h0_, h1_); sts8(aAl + sao3, l0_, l1_);                   \
    split_f4(rb0, h0_, h1_, l0_, l1_);                                        \
    sts8(bBh + sbo0, h0_, h1_); sts8(bBl + sbo0, l0_, l1_);                   \
    split_f4(rb1, h0_, h1_, l0_, l1_);                                        \
    sts8(bBh + sbo1, h0_, h1_); sts8(bBl + sbo1, l0_, l1_);                   \
} while (0)

#define MMAROW(I)                                                                             \
    mma16816(acc[I][0][0],acc[I][0][1],acc[I][0][2],acc[I][0][3], a0,a1,a2,a3, u0,u1);        \
    mma16816(acc[I][0][0],acc[I][0][1],acc[I][0][2],acc[I][0][3], a0,a1,a2,a3, w0,w1);        \
    mma16816(acc[I][0][0],acc[I][0][1],acc[I][0][2],acc[I][0][3], c0,c1,c2,c3, u0,u1);        \
    mma16816(acc[I][1][0],acc[I][1][1],acc[I][1][2],acc[I][1][3], a0,a1,a2,a3, u2,u3);        \
    mma16816(acc[I][1][0],acc[I][1][1],acc[I][1][2],acc[I][1][3], a0,a1,a2,a3, w2,w3);        \
    mma16816(acc[I][1][0],acc[I][1][1],acc[I][1][2],acc[I][1][3], c0,c1,c2,c3, u2,u3);        \
    mma16816(acc[I][2][0],acc[I][2][1],acc[I][2][2],acc[I][2][3], a0,a1,a2,a3, u4,u5);        \
    mma16816(acc[I][2][0],acc[I][2][1],acc[I][2][2],acc[I][2][3], a0,a1,a2,a3, w4,w5);        \
    mma16816(acc[I][2][0],acc[I][2][1],acc[I][2][2],acc[I][2][3], c0,c1,c2,c3, u4,u5);        \
    mma16816(acc[I][3][0],acc[I][3][1],acc[I][3][2],acc[I][3][3], a0,a1,a2,a3, u6,u7);        \
    mma16816(acc[I][3][0],acc[I][3][1],acc[I][3][2],acc[I][3][3], a0,a1,a2,a3, w6,w7);        \
    mma16816(acc[I][3][0],acc[I][3][1],acc[I][3][2],acc[I][3][3], c0,c1,c2,c3, u6,u7);

#define KSTEP(OA0, OA1, BEX) do {                                             \
    uint32_t u0,u1,u2,u3,u4,u5,u6,u7, w0,w1,w2,w3,w4,w5,w6,w7;                \
    ldm_x4_t(u0,u1,u2,u3, bBh + offB0 + (BEX));                               \
    ldm_x4_t(u4,u5,u6,u7, bBh + offB1 + (BEX));                               \
    ldm_x4_t(w0,w1,w2,w3, bBl + offB0 + (BEX));                               \
    ldm_x4_t(w4,w5,w6,w7, bBl + offB1 + (BEX));                               \
    {   uint32_t a0,a1,a2,a3, c0,c1,c2,c3;                                    \
        ldm_x4(a0,a1,a2,a3, aAh + (OA0));                                     \
        ldm_x4(c0,c1,c2,c3, aAl + (OA0));                                     \
        MMAROW(0)                                                             \
    }                                                                         \
    {   uint32_t a0,a1,a2,a3, c0,c1,c2,c3;                                    \
        ldm_x4(a0,a1,a2,a3, aAh + (OA1));                                     \
        ldm_x4(c0,c1,c2,c3, aAl + (OA1));                                     \
        MMAROW(1)                                                             \
    }                                                                         \
} while (0)

template <int KDIM, int NTOT, bool FIRST>
__global__ __launch_bounds__(256) void moe_gemm_mma(
    const float* __restrict__ xsrc,      // x for FIRST (else unused)
    const float* __restrict__ W,         // [E][KDIM][NTOT] fp32
    const float* __restrict__ bias)      // [E][NTOT] fp32
{
    constexpr int NS = KDIM / 32;
    int e = blockIdx.z;
    int seg0 = g_off[e];
    int M = g_off[e + 1] - seg0;
    int rowTile = blockIdx.x * 128;
    if (rowTile >= M) return;
    int colTile = blockIdx.y * 64;

    __shared__ int srow[128];
    __shared__ __align__(128) char sAbuf[16384];  // Ah 8K | Al 8K (bf16 128x32)
    __shared__ __align__(128) char sBbuf[8192];   // Bh 4K | Bl 4K (bf16 32x64)

    int tid = threadIdx.x, wid = tid >> 5, lane = tid & 31;

    if (tid < 128) {
        int r = rowTile + tid;
        int off;
        if (FIRST) {
            int tk = (r < M) ? g_tok[seg0 + r] : g_tok[seg0];
            off = tk * KDIM;
        } else {
            off = (seg0 + ((r < M) ? r : 0)) * KDIM;
        }
        srow[tid] = off;
    }
    __syncthreads();

    const float* srcA = FIRST ? xsrc : g_Hbuf;

    uint32_t aAh = smem_u32(sAbuf);
    uint32_t aAl = aAh + 8192;
    uint32_t bBh = smem_u32(sBbuf);
    uint32_t bBl = bBh + 4096;

    // ---- loader constants (per thread) ----
    // A: 4 float4s: idx = tid + q*256 in 0..1023; row = idx>>3, fi = idx&7
    int ia0 = tid, ia1 = tid + 256, ia2 = tid + 512, ia3 = tid + 768;
    int sr0 = srow[ia0 >> 3], sr1 = srow[ia1 >> 3];
    int sr2 = srow[ia2 >> 3], sr3 = srow[ia3 >> 3];
    int af0 = (ia0 & 7) * 4, af1 = (ia1 & 7) * 4, af2 = (ia2 & 7) * 4, af3 = (ia3 & 7) * 4;
    uint32_t sao0 = a_off(ia0 >> 3, (ia0 & 7) >> 1) + (ia0 & 1) * 8;
    uint32_t sao1 = a_off(ia1 >> 3, (ia1 & 7) >> 1) + (ia1 & 1) * 8;
    uint32_t sao2 = a_off(ia2 >> 3, (ia2 & 7) >> 1) + (ia2 & 1) * 8;
    uint32_t sao3 = a_off(ia3 >> 3, (ia3 & 7) >> 1) + (ia3 & 1) * 8;
    // B: 2 float4s: idx = tid + q*256 in 0..511; nG = idx&15, kk = idx>>4
    int ib0 = tid, ib1 = tid + 256;
    int kk0 = ib0 >> 4, kk1 = ib1 >> 4;
    int nG0 = ib0 & 15, nG1 = ib1 & 15;
    const float* pB0 = W + ((size_t)e * KDIM + kk0) * NTOT + colTile + nG0 * 4;
    const float* pB1 = W + ((size_t)e * KDIM + kk1) * NTOT + colTile + nG1 * 4;
    uint32_t sbo0 = b_off(kk0, nG0 >> 1) + (nG0 & 1) * 8;
    uint32_t sbo1 = b_off(kk1, nG1 >> 1) + (nG1 & 1) * 8;

    // ---- ldmatrix offsets ----
    int warpM = (wid & 3) * 32;
    int warpN = (wid >> 2) * 32;
    int rA = warpM + (lane & 15);
    uint32_t offA00 = a_off(rA,      (lane >> 4));        // mtile 0, ks 0
    uint32_t offA01 = a_off(rA,      2 + (lane >> 4));    // mtile 0, ks 1
    uint32_t offA10 = a_off(rA + 16, (lane >> 4));
    uint32_t offA11 = a_off(rA + 16, 2 + (lane >> 4));
    int kB = lane & 15;
    int nchBase = (warpN >> 3) + (lane >> 4);
    uint32_t offB0 = b_off(kB, nchBase);        // n-group pair 0 (cols warpN..+15)
    uint32_t offB1 = b_off(kB, nchBase + 2);    // n-group pair 1 (+16)
    // ks=1: k += 16 -> address += 16*128 = 2048 (swizzle invariant: (k&7) unchanged)

    float acc[2][4][4];
#pragma unroll
    for (int i = 0; i < 2; i++)
#pragma unroll
        for (int j = 0; j < 4; j++)
#pragma unroll
            for (int q = 0; q < 4; q++) acc[i][j][q] = 0.f;

    float4 ra0, ra1, ra2, ra3, rb0, rb1;
    LOADG(0);

    for (int s = 0; s < NS; s++) {
        __syncthreads();          // previous compute done -> smem reusable
        STORES();
        __syncthreads();          // smem tiles ready
        if (s + 1 < NS) LOADG(s + 1);
        KSTEP(offA00, offA10, 0);
        KSTEP(offA01, offA11, 2048);
    }

    // ----- epilogue -----
    const float* bcolBase = bias + (size_t)e * NTOT + colTile;
#pragma unroll
    for (int i = 0; i < 2; i++) {
        int r0 = warpM + i * 16 + (lane >> 2);
#pragma unroll
        for (int h = 0; h < 2; h++) {
            int grow = rowTile + r0 + h * 8;
            if (grow >= M) continue;
            size_t orow = (size_t)(seg0 + grow) * NTOT + colTile;
#pragma unroll
            for (int j = 0; j < 4; j++) {
                int col = warpN + j * 8 + (lane & 3) * 2;
                float v0 = acc[i][j][2 * h]     + bcolBase[col];
                float v1 = acc[i][j][2 * h + 1] + bcolBase[col + 1];
                if (FIRST) {
                    v0 = gelu_f(v0); v1 = gelu_f(v1);
                    *(float2*)(g_Hbuf + orow + col) = make_float2(v0, v1);
                } else {
                    *(float2*)(g_Ybuf + orow + col) = make_float2(v0, v1);
                }
            }
        }
    }
}

// ------------------------------- combine -----------------------------------
__global__ __launch_bounds__(256) void combine_kernel(float* __restrict__ out, int T) {
    size_t i = (size_t)blockIdx.x * 256 + threadIdx.x;
    size_t total = (size_t)T * (D_DIM / 4);
    if (i >= total) return;
    int t  = (int)(i >> 8);
    int d4 = (int)(i & 255);
    float w0 = g_w2[2 * t], w1 = g_w2[2 * t + 1];
    int s0 = g_slot[2 * t], s1 = g_slot[2 * t + 1];
    float4 a = ((const float4*)(g_Ybuf + (size_t)s0 * D_DIM))[d4];
    float4 b = ((const float4*)(g_Ybuf + (size_t)s1 * D_DIM))[d4];
    float4 o;
    o.x = w0 * a.x + w1 * b.x;
    o.y = w0 * a.y + w1 * b.y;
    o.z = w0 * a.z + w1 * b.z;
    o.w = w0 * a.w + w1 * b.w;
    ((float4*)(out + (size_t)t * D_DIM))[d4] = o;
}

// ------------------------------- launch ------------------------------------
extern "C" void kernel_launch(void* const* d_in, const int* in_sizes, int n_in,
                              void* d_out, int out_size)
{
    const float* x  = (const float*)d_in[0];
    const float* Wg = (const float*)d_in[1];
    const float* W1 = (const float*)d_in[2];
    const float* b1 = (const float*)d_in[3];
    const float* W2 = (const float*)d_in[4];
    const float* b2 = (const float*)d_in[5];
    float* out = (float*)d_out;

    int T = in_sizes[0] / D_DIM;
    if (T > MAXT) T = MAXT;

    int nblk = (T + 7) / 8;
    router_kernel<<<nblk, 256>>>(x, Wg, T);
    reduce_kernel<<<1, 32>>>(nblk, T, out + (size_t)T * D_DIM);
    scatter_kernel<<<(T + 255) / 256, 256>>>(T);

    int rowTilesMax = (T + 127) / 128;   // worst case: one expert takes all
    moe_gemm_mma<D_DIM, H_DIM, true ><<<dim3(rowTilesMax, H_DIM / 64, NE), 256>>>(x, W1, b1);
    moe_gemm_mma<H_DIM, D_DIM, false><<<dim3(rowTilesMax, D_DIM / 64, NE), 256>>>(nullptr, W2, b2);

    combine_kernel<<<(unsigned)(((size_t)T * 256 + 255) / 256), 256>>>(out, T);
}

// round 10
// speedup vs baseline: 2.2071x; 1.0550x over previous
#include <cuda_runtime.h>
#include <cuda_bf16.h>
#include <cstdint>
#include <math.h>

// ---------------------------------------------------------------------------
// MoE: B=4,S=2048,D=1024,H=4096,E=8,top2. T=8192.
// HMMA bf16 split GEMMs (Ah*Bh + Ah*Bl + Al*Bh), in-kernel fp32->bf16 split.
// R10: fast packed split (cvt.bf16x2 + prmt), double-buffered smem (1 bar per
// stage), STS.128 loaders, colTile-fastest grid for L2 reuse.
// Envelope: static smem <= 48KB, no cudaFuncSetAttribute, no cp.async,
// no lambdas, globals ~320MB.
// ---------------------------------------------------------------------------

#define D_DIM 1024
#define H_DIM 4096
#define NE    8
#define MAXT  8192
#define MAXSLOT (MAXT * 2)
#define MAXRBLK (MAXT / 8)

__device__ float g_partp[MAXRBLK * NE];
__device__ int   g_partc[MAXRBLK * NE];
__device__ float g_psum[NE];
__device__ int   g_cnt[NE];
__device__ int   g_off[NE + 1];
__device__ int   g_cur[NE];
__device__ int   g_idx2[MAXT * 2];
__device__ float g_w2[MAXT * 2];
__device__ int   g_slot[MAXT * 2];
__device__ int   g_tok[MAXSLOT];
__device__ float g_Hbuf[(size_t)MAXSLOT * H_DIM];  // 256 MB fp32
__device__ float g_Ybuf[(size_t)MAXSLOT * D_DIM];  // 64 MB fp32

// ------------------------------- helpers -----------------------------------
__device__ __forceinline__ uint32_t smem_u32(const void* p) {
    uint32_t a;
    asm("{ .reg .u64 t; cvta.to.shared.u64 t, %1; cvt.u32.u64 %0, t; }"
        : "=r"(a) : "l"(p));
    return a;
}
__device__ __forceinline__ void ldm_x4(uint32_t& r0, uint32_t& r1,
                                       uint32_t& r2, uint32_t& r3, uint32_t addr) {
    asm volatile("ldmatrix.sync.aligned.m8n8.x4.shared.b16 {%0,%1,%2,%3}, [%4];\n"
                 : "=r"(r0), "=r"(r1), "=r"(r2), "=r"(r3) : "r"(addr));
}
__device__ __forceinline__ void ldm_x4_t(uint32_t& r0, uint32_t& r1,
                                         uint32_t& r2, uint32_t& r3, uint32_t addr) {
    asm volatile("ldmatrix.sync.aligned.m8n8.x4.trans.shared.b16 {%0,%1,%2,%3}, [%4];\n"
                 : "=r"(r0), "=r"(r1), "=r"(r2), "=r"(r3) : "r"(addr));
}
__device__ __forceinline__ void mma16816(float& d0, float& d1, float& d2, float& d3,
                                         uint32_t a0, uint32_t a1, uint32_t a2, uint32_t a3,
                                         uint32_t b0, uint32_t b1) {
    asm volatile(
        "mma.sync.aligned.m16n8k16.row.col.f32.bf16.bf16.f32 "
        "{%0,%1,%2,%3}, {%4,%5,%6,%7}, {%8,%9}, {%0,%1,%2,%3};\n"
        : "+f"(d0), "+f"(d1), "+f"(d2), "+f"(d3)
        : "r"(a0), "r"(a1), "r"(a2), "r"(a3), "r"(b0), "r"(b1));
}
__device__ __forceinline__ void sts16(uint32_t addr, uint32_t x, uint32_t y,
                                      uint32_t z, uint32_t w) {
    asm volatile("st.shared.v4.b32 [%0], {%1,%2,%3,%4};\n"
                 :: "r"(addr), "r"(x), "r"(y), "r"(z), "r"(w) : "memory");
}
// A tile: [row][32 bf16] = 64B rows, 4 x 16B chunks, swizzle c^((row>>1)&3)
__device__ __forceinline__ uint32_t a_off(int row, int chunk) {
    return (uint32_t)((row * 4 + (chunk ^ ((row >> 1) & 3))) << 4);
}
// B tile: [k][64 bf16] = 128B rows, 8 x 16B chunks, swizzle c^(k&7)
__device__ __forceinline__ uint32_t b_off(int k, int chunk) {
    return (uint32_t)((k * 8 + (chunk ^ (k & 7))) << 4);
}
// fast split: 2 floats -> bf16x2 hi + bf16x2 lo (6 ops)
__device__ __forceinline__ void split2(float v0, float v1, uint32_t& h, uint32_t& l) {
    uint32_t hv, h0b, h1b;
    asm("cvt.rn.bf16x2.f32 %0, %1, %2;" : "=r"(hv) : "f"(v1), "f"(v0));
    asm("prmt.b32 %0, %1, 0, 0x1044;" : "=r"(h0b) : "r"(hv));   // h0 << 16
    asm("prmt.b32 %0, %1, 0, 0x3244;" : "=r"(h1b) : "r"(hv));   // h1 << 16
    float l0 = v0 - __uint_as_float(h0b);
    float l1 = v1 - __uint_as_float(h1b);
    asm("cvt.rn.bf16x2.f32 %0, %1, %2;" : "=r"(l) : "f"(l1), "f"(l0));
    h = hv;
}
__device__ __forceinline__ float gelu_f(float v) {
    return 0.5f * v * (1.0f + erff(v * 0.7071067811865476f));
}

// ------------------------------- router ------------------------------------
__global__ __launch_bounds__(256) void router_kernel(
    const float* __restrict__ x, const float* __restrict__ Wg, int T)
{
    __shared__ float sp[8][NE];
    __shared__ int   si[8][2];
    int tid = threadIdx.x, warp = tid >> 5, lane = tid & 31;
    int t = blockIdx.x * 8 + warp;

    float acc[NE];
#pragma unroll
    for (int e = 0; e < NE; e++) acc[e] = 0.f;
    if (t < T) {
        const float* xr = x + (size_t)t * D_DIM;
        for (int d = lane; d < D_DIM; d += 32) {
            float xv = xr[d];
            const float* wr = Wg + d * NE;
#pragma unroll
            for (int e = 0; e < NE; e++) acc[e] += xv * wr[e];
        }
    }
#pragma unroll
    for (int e = 0; e < NE; e++)
#pragma unroll
        for (int o = 16; o > 0; o >>= 1)
            acc[e] += __shfl_xor_sync(0xFFFFFFFFu, acc[e], o);

    if (lane == 0) {
        if (t < T) {
            float m = acc[0];
#pragma unroll
            for (int e = 1; e < NE; e++) m = fmaxf(m, acc[e]);
            float p[NE]; float s = 0.f;
#pragma unroll
            for (int e = 0; e < NE; e++) { p[e] = expf(acc[e] - m); s += p[e]; }
            float inv = 1.0f / s;
#pragma unroll
            for (int e = 0; e < NE; e++) p[e] *= inv;
            int i0 = 0; float v0 = p[0];
#pragma unroll
            for (int e = 1; e < NE; e++)
                if (p[e] > v0) { v0 = p[e]; i0 = e; }
            int i1 = -1; float v1 = -1.f;
#pragma unroll
            for (int e = 0; e < NE; e++) {
                if (e == i0) continue;
                if (p[e] > v1) { v1 = p[e]; i1 = e; }
            }
            float ws = v0 + v1;
            g_idx2[2 * t] = i0;  g_idx2[2 * t + 1] = i1;
            g_w2[2 * t] = v0 / ws;  g_w2[2 * t + 1] = v1 / ws;
#pragma unroll
            for (int e = 0; e < NE; e++) sp[warp][e] = p[e];
            si[warp][0] = i0; si[warp][1] = i1;
        } else {
#pragma unroll
            for (int e = 0; e < NE; e++) sp[warp][e] = 0.f;
            si[warp][0] = -1; si[warp][1] = -1;
        }
    }
    __syncthreads();
    if (tid < NE) {
        float s = 0.f; int c = 0;
#pragma unroll
        for (int w = 0; w < 8; w++) {
            s += sp[w][tid];
            if (si[w][0] == tid || si[w][1] == tid) c++;
        }
        g_partp[blockIdx.x * NE + tid] = s;
        g_partc[blockIdx.x * NE + tid] = c;
    }
}

__global__ void reduce_kernel(int nblk, int T, float* __restrict__ aux_out) {
    int tid = threadIdx.x;
    if (tid < NE) {
        float ps = 0.f; int cs = 0;
        for (int b = 0; b < nblk; b++) {
            ps += g_partp[b * NE + tid];
            cs += g_partc[b * NE + tid];
        }
        g_psum[tid] = ps; g_cnt[tid] = cs; g_cur[tid] = 0;
    }
    __syncthreads();
    if (tid == 0) {
        int off = 0;
        for (int e = 0; e < NE; e++) { g_off[e] = off; off += g_cnt[e]; }
        g_off[NE] = off;
        float invT = 1.0f / (float)T;
        float aux = 0.f;
        for (int e = 0; e < NE; e++)
            aux += ((float)g_cnt[e] * invT) * (g_psum[e] * invT);
        *aux_out = (float)NE * aux;
    }
}

__global__ void scatter_kernel(int T) {
    int t = blockIdx.x * 256 + threadIdx.x;
    if (t >= T) return;
#pragma unroll
    for (int k = 0; k < 2; k++) {
        int e = g_idx2[2 * t + k];
        int pos = atomicAdd(&g_cur[e], 1);
        int s = g_off[e] + pos;
        g_tok[s] = t;
        g_slot[2 * t + k] = s;
    }
}

// --------------------------- HMMA grouped GEMM -----------------------------
// CTA 128(M) x 64(N), BK=32. 8 warps (4x2), warp tile 32x32.
// Double-buffered smem (2 x 24KB), 1 barrier/stage, register staging:
//   iter s: STS(stage s+1 -> other buf); LDG(stage s+2); MMA(stage s); bar
#define BUF_BYTES 24576   // Ah 8K | Al 8K | Bh 4K | Bl 4K

#define LOADG(S_) do { int k0_ = (S_) * 32;                                   \
    ra0 = *(const float4*)(pA0 + k0_);                                        \
    ra1 = *(const float4*)(pA0 + k0_ + 4);                                    \
    ra2 = *(const float4*)(pA1 + k0_);                                        \
    ra3 = *(const float4*)(pA1 + k0_ + 4);                                    \
    rb0 = *(const float4*)(pB + (size_t)k0_ * NTOT);                          \
    rb1 = *(const float4*)(pB + (size_t)k0_ * NTOT + 4);                      \
} while (0)

#define STORES(BB) do {                                                       \
    uint32_t h0_,h1_,h2_,h3_, l0_,l1_,l2_,l3_;                                \
    split2(ra0.x, ra0.y, h0_, l0_);  split2(ra0.z, ra0.w, h1_, l1_);          \
    split2(ra1.x, ra1.y, h2_, l2_);  split2(ra1.z, ra1.w, h3_, l3_);          \
    sts16((BB) + sA0, h0_, h1_, h2_, h3_);                                    \
    sts16((BB) + 8192 + sA0, l0_, l1_, l2_, l3_);                             \
    split2(ra2.x, ra2.y, h0_, l0_);  split2(ra2.z, ra2.w, h1_, l1_);          \
    split2(ra3.x, ra3.y, h2_, l2_);  split2(ra3.z, ra3.w, h3_, l3_);          \
    sts16((BB) + sA1, h0_, h1_, h2_, h3_);                                    \
    sts16((BB) + 8192 + sA1, l0_, l1_, l2_, l3_);                             \
    split2(rb0.x, rb0.y, h0_, l0_);  split2(rb0.z, rb0.w, h1_, l1_);          \
    split2(rb1.x, rb1.y, h2_, l2_);  split2(rb1.z, rb1.w, h3_, l3_);          \
    sts16((BB) + 16384 + sB, h0_, h1_, h2_, h3_);                             \
    sts16((BB) + 20480 + sB, l0_, l1_, l2_, l3_);                             \
} while (0)

#define MMAROW(I)                                                                             \
    mma16816(acc[I][0][0],acc[I][0][1],acc[I][0][2],acc[I][0][3], a0,a1,a2,a3, u0,u1);        \
    mma16816(acc[I][0][0],acc[I][0][1],acc[I][0][2],acc[I][0][3], a0,a1,a2,a3, w0,w1);        \
    mma16816(acc[I][0][0],acc[I][0][1],acc[I][0][2],acc[I][0][3], c0,c1,c2,c3, u0,u1);        \
    mma16816(acc[I][1][0],acc[I][1][1],acc[I][1][2],acc[I][1][3], a0,a1,a2,a3, u2,u3);        \
    mma16816(acc[I][1][0],acc[I][1][1],acc[I][1][2],acc[I][1][3], a0,a1,a2,a3, w2,w3);        \
    mma16816(acc[I][1][0],acc[I][1][1],acc[I][1][2],acc[I][1][3], c0,c1,c2,c3, u2,u3);        \
    mma16816(acc[I][2][0],acc[I][2][1],acc[I][2][2],acc[I][2][3], a0,a1,a2,a3, u4,u5);        \
    mma16816(acc[I][2][0],acc[I][2][1],acc[I][2][2],acc[I][2][3], a0,a1,a2,a3, w4,w5);        \
    mma16816(acc[I][2][0],acc[I][2][1],acc[I][2][2],acc[I][2][3], c0,c1,c2,c3, u4,u5);        \
    mma16816(acc[I][3][0],acc[I][3][1],acc[I][3][2],acc[I][3][3], a0,a1,a2,a3, u6,u7);        \
    mma16816(acc[I][3][0],acc[I][3][1],acc[I][3][2],acc[I][3][3], a0,a1,a2,a3, w6,w7);        \
    mma16816(acc[I][3][0],acc[I][3][1],acc[I][3][2],acc[I][3][3], c0,c1,c2,c3, u6,u7);

#define KSTEP(BB, OA0, OA1, BEX) do {                                         \
    uint32_t u0,u1,u2,u3,u4,u5,u6,u7, w0,w1,w2,w3,w4,w5,w6,w7;                \
    ldm_x4_t(u0,u1,u2,u3, (BB) + 16384 + offB0 + (BEX));                      \
    ldm_x4_t(u4,u5,u6,u7, (BB) + 16384 + offB1 + (BEX));                      \
    ldm_x4_t(w0,w1,w2,w3, (BB) + 20480 + offB0 + (BEX));                      \
    ldm_x4_t(w4,w5,w6,w7, (BB) + 20480 + offB1 + (BEX));                      \
    {   uint32_t a0,a1,a2,a3, c0,c1,c2,c3;                                    \
        ldm_x4(a0,a1,a2,a3, (BB) + (OA0));                                    \
        ldm_x4(c0,c1,c2,c3, (BB) + 8192 + (OA0));                             \
        MMAROW(0)                                                             \
    }                                                                         \
    {   uint32_t a0,a1,a2,a3, c0,c1,c2,c3;                                    \
        ldm_x4(a0,a1,a2,a3, (BB) + (OA1));                                    \
        ldm_x4(c0,c1,c2,c3, (BB) + 8192 + (OA1));                             \
        MMAROW(1)                                                             \
    }                                                                         \
} while (0)

template <int KDIM, int NTOT, bool FIRST>
__global__ __launch_bounds__(256, 2) void moe_gemm_mma(
    const float* __restrict__ xsrc,      // x for FIRST (else unused)
    const float* __restrict__ W,         // [E][KDIM][NTOT] fp32
    const float* __restrict__ bias)      // [E][NTOT] fp32
{
    constexpr int NS = KDIM / 32;
    int e = blockIdx.z;
    int seg0 = g_off[e];
    int M = g_off[e + 1] - seg0;
    int rowTile = blockIdx.y * 128;       // colTile-fastest grid (L2 reuse)
    if (rowTile >= M) return;
    int colTile = blockIdx.x * 64;

    __shared__ __align__(128) char sbuf[2][BUF_BYTES];   // exactly 48 KB

    int tid = threadIdx.x, wid = tid >> 5, lane = tid & 31;
    const float* srcA = FIRST ? xsrc : g_Hbuf;

    // ---- per-thread loader constants (no smem srow table) ----
    int arow0 = tid >> 2;                 // 0..63
    int arow1 = 64 + (tid >> 3 >> 0);     // placeholder; fixed below
    arow1 = 64 + (tid >> 2);
    int ap = tid & 3;
    int r0 = rowTile + arow0, r1 = rowTile + arow1;
    int gr0, gr1;
    if (FIRST) {
        gr0 = ((r0 < M) ? g_tok[seg0 + r0] : g_tok[seg0]) * KDIM;
        gr1 = ((r1 < M) ? g_tok[seg0 + r1] : g_tok[seg0]) * KDIM;
    } else {
        gr0 = (seg0 + ((r0 < M) ? r0 : 0)) * KDIM;
        gr1 = (seg0 + ((r1 < M) ? r1 : 0)) * KDIM;
    }
    const float* pA0 = srcA + gr0 + ap * 8;
    const float* pA1 = srcA + gr1 + ap * 8;
    uint32_t sA0 = a_off(arow0, ap);
    uint32_t sA1 = a_off(arow1, ap);
    int bk = tid >> 3, bp = tid & 7;
    const float* pB = W + ((size_t)e * KDIM + bk) * NTOT + colTile + bp * 8;
    uint32_t sB = b_off(bk, bp);

    // ---- ldmatrix offsets ----
    int warpM = (wid & 3) * 32;
    int warpN = (wid >> 2) * 32;
    int rA = warpM + (lane & 15);
    uint32_t offA00 = a_off(rA,      (lane >> 4));        // mtile 0, ks 0
    uint32_t offA01 = a_off(rA,      2 + (lane >> 4));    // mtile 0, ks 1
    uint32_t offA10 = a_off(rA + 16, (lane >> 4));
    uint32_t offA11 = a_off(rA + 16, 2 + (lane >> 4));
    int kB = lane & 15;
    int nchBase = (warpN >> 3) + (lane >> 4);
    uint32_t offB0 = b_off(kB, nchBase);
    uint32_t offB1 = b_off(kB, nchBase + 2);
    // ks=1: k += 16 -> +2048 bytes (swizzle uses k&7, invariant)

    float acc[2][4][4];
#pragma unroll
    for (int i = 0; i < 2; i++)
#pragma unroll
        for (int j = 0; j < 4; j++)
#pragma unroll
            for (int q = 0; q < 4; q++) acc[i][j][q] = 0.f;

    uint32_t sb0 = smem_u32(sbuf);
    float4 ra0, ra1, ra2, ra3, rb0, rb1;

    // prologue: stage0 -> buf0; stage1 -> regs
    LOADG(0);
    STORES(sb0);
    LOADG(1);
    __syncthreads();

    for (int s = 0; s < NS; s++) {
        uint32_t cur = sb0 + (uint32_t)(s & 1) * BUF_BYTES;
        uint32_t nxt = sb0 + (uint32_t)((s + 1) & 1) * BUF_BYTES;
        if (s + 1 < NS) STORES(nxt);
        if (s + 2 < NS) LOADG(s + 2);
        KSTEP(cur, offA00, offA10, 0);
        KSTEP(cur, offA01, offA11, 2048);
        __syncthreads();
    }

    // ----- epilogue -----
    const float* bcolBase = bias + (size_t)e * NTOT + colTile;
#pragma unroll
    for (int i = 0; i < 2; i++) {
        int r0e = warpM + i * 16 + (lane >> 2);
#pragma unroll
        for (int h = 0; h < 2; h++) {
            int grow = rowTile + r0e + h * 8;
            if (grow >= M) continue;
            size_t orow = (size_t)(seg0 + grow) * NTOT + colTile;
#pragma unroll
            for (int j = 0; j < 4; j++) {
                int col = warpN + j * 8 + (lane & 3) * 2;
                float v0 = acc[i][j][2 * h]     + bcolBase[col];
                float v1 = acc[i][j][2 * h + 1] + bcolBase[col + 1];
                if (FIRST) {
                    v0 = gelu_f(v0); v1 = gelu_f(v1);
                    *(float2*)(g_Hbuf + orow + col) = make_float2(v0, v1);
                } else {
                    *(float2*)(g_Ybuf + orow + col) = make_float2(v0, v1);
                }
            }
        }
    }
}

// ------------------------------- combine -----------------------------------
__global__ __launch_bounds__(256) void combine_kernel(float* __restrict__ out, int T) {
    size_t i = (size_t)blockIdx.x * 256 + threadIdx.x;
    size_t total = (size_t)T * (D_DIM / 4);
    if (i >= total) return;
    int t  = (int)(i >> 8);
    int d4 = (int)(i & 255);
    float w0 = g_w2[2 * t], w1 = g_w2[2 * t + 1];
    int s0 = g_slot[2 * t], s1 = g_slot[2 * t + 1];
    float4 a = ((const float4*)(g_Ybuf + (size_t)s0 * D_DIM))[d4];
    float4 b = ((const float4*)(g_Ybuf + (size_t)s1 * D_DIM))[d4];
    float4 o;
    o.x = w0 * a.x + w1 * b.x;
    o.y = w0 * a.y + w1 * b.y;
    o.z = w0 * a.z + w1 * b.z;
    o.w = w0 * a.w + w1 * b.w;
    ((float4*)(out + (size_t)t * D_DIM))[d4] = o;
}

// ------------------------------- launch ------------------------------------
extern "C" void kernel_launch(void* const* d_in, const int* in_sizes, int n_in,
                              void* d_out, int out_size)
{
    const float* x  = (const float*)d_in[0];
    const float* Wg = (const float*)d_in[1];
    const float* W1 = (const float*)d_in[2];
    const float* b1 = (const float*)d_in[3];
    const float* W2 = (const float*)d_in[4];
    const float* b2 = (const float*)d_in[5];
    float* out = (float*)d_out;

    int T = in_sizes[0] / D_DIM;
    if (T > MAXT) T = MAXT;

    int nblk = (T + 7) / 8;
    router_kernel<<<nblk, 256>>>(x, Wg, T);
    reduce_kernel<<<1, 32>>>(nblk, T, out + (size_t)T * D_DIM);
    scatter_kernel<<<(T + 255) / 256, 256>>>(T);

    int rowTilesMax = (T + 127) / 128;   // worst case: one expert takes all
    // colTile-fastest grid: concurrent CTAs share A/H rows; W stays in L2
    moe_gemm_mma<D_DIM, H_DIM, true ><<<dim3(H_DIM / 64, rowTilesMax, NE), 256>>>(x, W1, b1);
    moe_gemm_mma<H_DIM, D_DIM, false><<<dim3(D_DIM / 64, rowTilesMax, NE), 256>>>(nullptr, W2, b2);

    combine_kernel<<<(unsigned)(((size_t)T * 256 + 255) / 256), 256>>>(out, T);
}

// round 12
// speedup vs baseline: 2.5711x; 1.1649x over previous
#include <cuda_runtime.h>
#include <cuda_bf16.h>
#include <cstdint>
#include <math.h>

// ---------------------------------------------------------------------------
// MoE: B=4,S=2048,D=1024,H=4096,E=8,top2. T=8192.
// HMMA bf16 split GEMMs (Ah*Bh + Ah*Bl + Al*Bh), in-kernel fp32->bf16 split.
// R11/R12: warp tile 64x32 (2Mx4N layout, CTA 128x128, BK=16) to cut smem
// bytes/MMA ~35% (crossbar-bound per R10 ncu). Double buffer 2x16KB = 32KB.
// Envelope: static smem <= 48KB, no cudaFuncSetAttribute, no cp.async,
// no lambdas, globals ~320MB.
// ---------------------------------------------------------------------------

#define D_DIM 1024
#define H_DIM 4096
#define NE    8
#define MAXT  8192
#define MAXSLOT (MAXT * 2)
#define MAXRBLK (MAXT / 8)

__device__ float g_partp[MAXRBLK * NE];
__device__ int   g_partc[MAXRBLK * NE];
__device__ float g_psum[NE];
__device__ int   g_cnt[NE];
__device__ int   g_off[NE + 1];
__device__ int   g_cur[NE];
__device__ int   g_idx2[MAXT * 2];
__device__ float g_w2[MAXT * 2];
__device__ int   g_slot[MAXT * 2];
__device__ int   g_tok[MAXSLOT];
__device__ float g_Hbuf[(size_t)MAXSLOT * H_DIM];  // 256 MB fp32
__device__ float g_Ybuf[(size_t)MAXSLOT * D_DIM];  // 64 MB fp32

// ------------------------------- helpers -----------------------------------
__device__ __forceinline__ uint32_t smem_u32(const void* p) {
    uint32_t a;
    asm("{ .reg .u64 t; cvta.to.shared.u64 t, %1; cvt.u32.u64 %0, t; }"
        : "=r"(a) : "l"(p));
    return a;
}
__device__ __forceinline__ void ldm_x4(uint32_t& r0, uint32_t& r1,
                                       uint32_t& r2, uint32_t& r3, uint32_t addr) {
    asm volatile("ldmatrix.sync.aligned.m8n8.x4.shared.b16 {%0,%1,%2,%3}, [%4];\n"
                 : "=r"(r0), "=r"(r1), "=r"(r2), "=r"(r3) : "r"(addr));
}
__device__ __forceinline__ void ldm_x4_t(uint32_t& r0, uint32_t& r1,
                                         uint32_t& r2, uint32_t& r3, uint32_t addr) {
    asm volatile("ldmatrix.sync.aligned.m8n8.x4.trans.shared.b16 {%0,%1,%2,%3}, [%4];\n"
                 : "=r"(r0), "=r"(r1), "=r"(r2), "=r"(r3) : "r"(addr));
}
__device__ __forceinline__ void mma16816(float& d0, float& d1, float& d2, float& d3,
                                         uint32_t a0, uint32_t a1, uint32_t a2, uint32_t a3,
                                         uint32_t b0, uint32_t b1) {
    asm volatile(
        "mma.sync.aligned.m16n8k16.row.col.f32.bf16.bf16.f32 "
        "{%0,%1,%2,%3}, {%4,%5,%6,%7}, {%8,%9}, {%0,%1,%2,%3};\n"
        : "+f"(d0), "+f"(d1), "+f"(d2), "+f"(d3)
        : "r"(a0), "r"(a1), "r"(a2), "r"(a3), "r"(b0), "r"(b1));
}
__device__ __forceinline__ void sts16(uint32_t addr, uint32_t x, uint32_t y,
                                      uint32_t z, uint32_t w) {
    asm volatile("st.shared.v4.b32 [%0], {%1,%2,%3,%4};\n"
                 :: "r"(addr), "r"(x), "r"(y), "r"(z), "r"(w) : "memory");
}
// A tile (BK=16): 128 rows x 16 bf16 = 32B/row, packed 2 rows per 64B line.
// sub = (row&1)*2 + c (c = k-chunk 0/1), phys = sub ^ ((row>>2)&1).
// Verified conflict-free for STS.128 and ldmatrix (granules distinct mod 8).
__device__ __forceinline__ uint32_t a16_off(int row, int c) {
    int sub = (row & 1) * 2 + c;
    return (uint32_t)(((row >> 1) * 4 + (sub ^ ((row >> 2) & 1))) << 4);
}
// B tile (BK=16): 16 k-rows x 128 bf16 = 256B/row, 16 chunks, swizzle c^(k&7).
__device__ __forceinline__ uint32_t b16_off(int k, int c) {
    return (uint32_t)((k * 16 + (c ^ (k & 7))) << 4);
}
// fast split: 2 floats -> bf16x2 hi + bf16x2 lo (6 ops)
__device__ __forceinline__ void split2(float v0, float v1, uint32_t& h, uint32_t& l) {
    uint32_t hv, h0b, h1b;
    asm("cvt.rn.bf16x2.f32 %0, %1, %2;" : "=r"(hv) : "f"(v1), "f"(v0));
    asm("prmt.b32 %0, %1, 0, 0x1044;" : "=r"(h0b) : "r"(hv));   // h0 << 16
    asm("prmt.b32 %0, %1, 0, 0x3244;" : "=r"(h1b) : "r"(hv));   // h1 << 16
    float l0 = v0 - __uint_as_float(h0b);
    float l1 = v1 - __uint_as_float(h1b);
    asm("cvt.rn.bf16x2.f32 %0, %1, %2;" : "=r"(l) : "f"(l1), "f"(l0));
    h = hv;
}
__device__ __forceinline__ float gelu_f(float v) {
    return 0.5f * v * (1.0f + erff(v * 0.7071067811865476f));
}

// ------------------------------- router ------------------------------------
__global__ __launch_bounds__(256) void router_kernel(
    const float* __restrict__ x, const float* __restrict__ Wg, int T)
{
    __shared__ float sp[8][NE];
    __shared__ int   si[8][2];
    int tid = threadIdx.x, warp = tid >> 5, lane = tid & 31;
    int t = blockIdx.x * 8 + warp;

    float acc[NE];
#pragma unroll
    for (int e = 0; e < NE; e++) acc[e] = 0.f;
    if (t < T) {
        const float* xr = x + (size_t)t * D_DIM;
        for (int d = lane; d < D_DIM; d += 32) {
            float xv = xr[d];
            const float* wr = Wg + d * NE;
#pragma unroll
            for (int e = 0; e < NE; e++) acc[e] += xv * wr[e];
        }
    }
#pragma unroll
    for (int e = 0; e < NE; e++)
#pragma unroll
        for (int o = 16; o > 0; o >>= 1)
            acc[e] += __shfl_xor_sync(0xFFFFFFFFu, acc[e], o);

    if (lane == 0) {
        if (t < T) {
            float m = acc[0];
#pragma unroll
            for (int e = 1; e < NE; e++) m = fmaxf(m, acc[e]);
            float p[NE]; float s = 0.f;
#pragma unroll
            for (int e = 0; e < NE; e++) { p[e] = expf(acc[e] - m); s += p[e]; }
            float inv = 1.0f / s;
#pragma unroll
            for (int e = 0; e < NE; e++) p[e] *= inv;
            int i0 = 0; float v0 = p[0];
#pragma unroll
            for (int e = 1; e < NE; e++)
                if (p[e] > v0) { v0 = p[e]; i0 = e; }
            int i1 = -1; float v1 = -1.f;
#pragma unroll
            for (int e = 0; e < NE; e++) {
                if (e == i0) continue;
                if (p[e] > v1) { v1 = p[e]; i1 = e; }
            }
            float ws = v0 + v1;
            g_idx2[2 * t] = i0;  g_idx2[2 * t + 1] = i1;
            g_w2[2 * t] = v0 / ws;  g_w2[2 * t + 1] = v1 / ws;
#pragma unroll
            for (int e = 0; e < NE; e++) sp[warp][e] = p[e];
            si[warp][0] = i0; si[warp][1] = i1;
        } else {
#pragma unroll
            for (int e = 0; e < NE; e++) sp[warp][e] = 0.f;
            si[warp][0] = -1; si[warp][1] = -1;
        }
    }
    __syncthreads();
    if (tid < NE) {
        float s = 0.f; int c = 0;
#pragma unroll
        for (int w = 0; w < 8; w++) {
            s += sp[w][tid];
            if (si[w][0] == tid || si[w][1] == tid) c++;
        }
        g_partp[blockIdx.x * NE + tid] = s;
        g_partc[blockIdx.x * NE + tid] = c;
    }
}

__global__ void reduce_kernel(int nblk, int T, float* __restrict__ aux_out) {
    int tid = threadIdx.x;
    if (tid < NE) {
        float ps = 0.f; int cs = 0;
        for (int b = 0; b < nblk; b++) {
            ps += g_partp[b * NE + tid];
            cs += g_partc[b * NE + tid];
        }
        g_psum[tid] = ps; g_cnt[tid] = cs; g_cur[tid] = 0;
    }
    __syncthreads();
    if (tid == 0) {
        int off = 0;
        for (int e = 0; e < NE; e++) { g_off[e] = off; off += g_cnt[e]; }
        g_off[NE] = off;
        float invT = 1.0f / (float)T;
        float aux = 0.f;
        for (int e = 0; e < NE; e++)
            aux += ((float)g_cnt[e] * invT) * (g_psum[e] * invT);
        *aux_out = (float)NE * aux;
    }
}

__global__ void scatter_kernel(int T) {
    int t = blockIdx.x * 256 + threadIdx.x;
    if (t >= T) return;
#pragma unroll
    for (int k = 0; k < 2; k++) {
        int e = g_idx2[2 * t + k];
        int pos = atomicAdd(&g_cur[e], 1);
        int s = g_off[e] + pos;
        g_tok[s] = t;
        g_slot[2 * t + k] = s;
    }
}

// --------------------------- HMMA grouped GEMM -----------------------------
// CTA 128(M) x 128(N), BK=16. 8 warps (2Mx4N), warp tile 64x32.
// Double-buffered smem 2 x 16KB; per stage: Ah 4K | Al 4K | Bh 4K | Bl 4K.
// iter s: STORES(stage s+1 -> other buf); LDG(stage s+2); MMA(stage s); bar.
#define BUF_BYTES 16384

#define LOADG(S_) do { int k0_ = (S_) * 16;                                   \
    ra0 = *(const float4*)(pA + k0_);                                         \
    ra1 = *(const float4*)(pA + k0_ + 4);                                     \
    rb0 = *(const float4*)(pB + (size_t)k0_ * NTOT);                          \
    rb1 = *(const float4*)(pB + (size_t)k0_ * NTOT + 4);                      \
} while (0)

#define STORES(BB) do {                                                       \
    uint32_t h0_,h1_,h2_,h3_, l0_,l1_,l2_,l3_;                                \
    split2(ra0.x, ra0.y, h0_, l0_);  split2(ra0.z, ra0.w, h1_, l1_);          \
    split2(ra1.x, ra1.y, h2_, l2_);  split2(ra1.z, ra1.w, h3_, l3_);          \
    sts16((BB) + sAo, h0_, h1_, h2_, h3_);                                    \
    sts16((BB) + 4096 + sAo, l0_, l1_, l2_, l3_);                             \
    split2(rb0.x, rb0.y, h0_, l0_);  split2(rb0.z, rb0.w, h1_, l1_);          \
    split2(rb1.x, rb1.y, h2_, l2_);  split2(rb1.z, rb1.w, h3_, l3_);          \
    sts16((BB) + 8192 + sBo, h0_, h1_, h2_, h3_);                             \
    sts16((BB) + 12288 + sBo, l0_, l1_, l2_, l3_);                            \
} while (0)

#define MMAROW(I)                                                                             \
    mma16816(acc[I][0][0],acc[I][0][1],acc[I][0][2],acc[I][0][3], a0,a1,a2,a3, u0,u1);        \
    mma16816(acc[I][0][0],acc[I][0][1],acc[I][0][2],acc[I][0][3], a0,a1,a2,a3, w0,w1);        \
    mma16816(acc[I][0][0],acc[I][0][1],acc[I][0][2],acc[I][0][3], c0,c1,c2,c3, u0,u1);        \
    mma16816(acc[I][1][0],acc[I][1][1],acc[I][1][2],acc[I][1][3], a0,a1,a2,a3, u2,u3);        \
    mma16816(acc[I][1][0],acc[I][1][1],acc[I][1][2],acc[I][1][3], a0,a1,a2,a3, w2,w3);        \
    mma16816(acc[I][1][0],acc[I][1][1],acc[I][1][2],acc[I][1][3], c0,c1,c2,c3, u2,u3);        \
    mma16816(acc[I][2][0],acc[I][2][1],acc[I][2][2],acc[I][2][3], a0,a1,a2,a3, u4,u5);        \
    mma16816(acc[I][2][0],acc[I][2][1],acc[I][2][2],acc[I][2][3], a0,a1,a2,a3, w4,w5);        \
    mma16816(acc[I][2][0],acc[I][2][1],acc[I][2][2],acc[I][2][3], c0,c1,c2,c3, u4,u5);        \
    mma16816(acc[I][3][0],acc[I][3][1],acc[I][3][2],acc[I][3][3], a0,a1,a2,a3, u6,u7);        \
    mma16816(acc[I][3][0],acc[I][3][1],acc[I][3][2],acc[I][3][3], a0,a1,a2,a3, w6,w7);        \
    mma16816(acc[I][3][0],acc[I][3][1],acc[I][3][2],acc[I][3][3], c0,c1,c2,c3, u6,u7);

#define KSTEP16(BB) do {                                                      \
    uint32_t u0,u1,u2,u3,u4,u5,u6,u7, w0,w1,w2,w3,w4,w5,w6,w7;                \
    ldm_x4_t(u0,u1,u2,u3, (BB) + 8192 + offB0);                               \
    ldm_x4_t(u4,u5,u6,u7, (BB) + 8192 + offB1);                               \
    ldm_x4_t(w0,w1,w2,w3, (BB) + 12288 + offB0);                              \
    ldm_x4_t(w4,w5,w6,w7, (BB) + 12288 + offB1);                              \
    {   uint32_t a0,a1,a2,a3, c0,c1,c2,c3;                                    \
        ldm_x4(a0,a1,a2,a3, (BB) + offA0);                                    \
        ldm_x4(c0,c1,c2,c3, (BB) + 4096 + offA0);                             \
        MMAROW(0)                                                             \
    }                                                                         \
    {   uint32_t a0,a1,a2,a3, c0,c1,c2,c3;                                    \
        ldm_x4(a0,a1,a2,a3, (BB) + offA1);                                    \
        ldm_x4(c0,c1,c2,c3, (BB) + 4096 + offA1);                             \
        MMAROW(1)                                                             \
    }                                                                         \
    {   uint32_t a0,a1,a2,a3, c0,c1,c2,c3;                                    \
        ldm_x4(a0,a1,a2,a3, (BB) + offA2);                                    \
        ldm_x4(c0,c1,c2,c3, (BB) + 4096 + offA2);                             \
        MMAROW(2)                                                             \
    }                                                                         \
    {   uint32_t a0,a1,a2,a3, c0,c1,c2,c3;                                    \
        ldm_x4(a0,a1,a2,a3, (BB) + offA3);                                    \
        ldm_x4(c0,c1,c2,c3, (BB) + 4096 + offA3);                             \
        MMAROW(3)                                                             \
    }                                                                         \
} while (0)

template <int KDIM, int NTOT, bool FIRST>
__global__ __launch_bounds__(256, 2) void moe_gemm_mma(
    const float* __restrict__ xsrc,      // x for FIRST (else unused)
    const float* __restrict__ W,         // [E][KDIM][NTOT] fp32
    const float* __restrict__ bias)      // [E][NTOT] fp32
{
    constexpr int NS = KDIM / 16;
    int e = blockIdx.z;
    int seg0 = g_off[e];
    int M = g_off[e + 1] - seg0;
    int rowTile = blockIdx.y * 128;       // colTile-fastest grid (L2 reuse)
    if (rowTile >= M) return;
    int colTile = blockIdx.x * 128;

    __shared__ __align__(128) char sbuf[2][BUF_BYTES];   // 32 KB

    int tid = threadIdx.x, wid = tid >> 5, lane = tid & 31;
    const float* srcA = FIRST ? xsrc : g_Hbuf;

    // ---- per-thread loader constants ----
    // A: 1 granule = 8 floats: row = tid>>1 (0..127), c = tid&1
    int arow = tid >> 1, ac = tid & 1;
    int rA_g = rowTile + arow;
    int groff;
    if (FIRST) {
        groff = ((rA_g < M) ? g_tok[seg0 + rA_g] : g_tok[seg0]) * KDIM;
    } else {
        groff = (seg0 + ((rA_g < M) ? rA_g : 0)) * KDIM;
    }
    const float* pA = srcA + groff + ac * 8;
    uint32_t sAo = a16_off(arow, ac);
    // B: 1 granule = 8 floats: k = tid>>4 (0..15), c = tid&15
    int bk = tid >> 4, bc = tid & 15;
    const float* pB = W + ((size_t)e * KDIM + bk) * NTOT + colTile + bc * 8;
    uint32_t sBo = b16_off(bk, bc);

    // ---- ldmatrix offsets ----
    int warpM = (wid & 1) * 64;
    int warpN = (wid >> 1) * 32;
    int lrow = lane & 15, lch = lane >> 4;
    uint32_t offA0 = a16_off(warpM + 0  + lrow, lch);
    uint32_t offA1 = a16_off(warpM + 16 + lrow, lch);
    uint32_t offA2 = a16_off(warpM + 32 + lrow, lch);
    uint32_t offA3 = a16_off(warpM + 48 + lrow, lch);
    int nb = warpN >> 3;
    uint32_t offB0 = b16_off(lane & 15, nb + (lane >> 4));
    uint32_t offB1 = b16_off(lane & 15, nb + 2 + (lane >> 4));

    float acc[4][4][4];
#pragma unroll
    for (int i = 0; i < 4; i++)
#pragma unroll
        for (int j = 0; j < 4; j++)
#pragma unroll
            for (int q = 0; q < 4; q++) acc[i][j][q] = 0.f;

    uint32_t sb0 = smem_u32(sbuf);
    float4 ra0, ra1, rb0, rb1;

    // prologue
    LOADG(0);
    STORES(sb0);
    LOADG(1);
    __syncthreads();

    for (int s = 0; s < NS; s++) {
        uint32_t cur = sb0 + (uint32_t)(s & 1) * BUF_BYTES;
        uint32_t nxt = sb0 + (uint32_t)((s + 1) & 1) * BUF_BYTES;
        if (s + 1 < NS) STORES(nxt);
        if (s + 2 < NS) LOADG(s + 2);
        KSTEP16(cur);
        __syncthreads();
    }

    // ----- epilogue -----
    const float* bcolBase = bias + (size_t)e * NTOT + colTile;
#pragma unroll
    for (int i = 0; i < 4; i++) {
        int r0e = warpM + i * 16 + (lane >> 2);
#pragma unroll
        for (int h = 0; h < 2; h++) {
            int grow = rowTile + r0e + h * 8;
            if (grow >= M) continue;
            size_t orow = (size_t)(seg0 + grow) * NTOT + colTile;
#pragma unroll
            for (int j = 0; j < 4; j++) {
                int col = warpN + j * 8 + (lane & 3) * 2;
                float v0 = acc[i][j][2 * h]     + bcolBase[col];
                float v1 = acc[i][j][2 * h + 1] + bcolBase[col + 1];
                if (FIRST) {
                    v0 = gelu_f(v0); v1 = gelu_f(v1);
                    *(float2*)(g_Hbuf + orow + col) = make_float2(v0, v1);
                } else {
                    *(float2*)(g_Ybuf + orow + col) = make_float2(v0, v1);
                }
            }
        }
    }
}

// ------------------------------- combine -----------------------------------
__global__ __launch_bounds__(256) void combine_kernel(float* __restrict__ out, int T) {
    size_t i = (size_t)blockIdx.x * 256 + threadIdx.x;
    size_t total = (size_t)T * (D_DIM / 4);
    if (i >= total) return;
    int t  = (int)(i >> 8);
    int d4 = (int)(i & 255);
    float w0 = g_w2[2 * t], w1 = g_w2[2 * t + 1];
    int s0 = g_slot[2 * t], s1 = g_slot[2 * t + 1];
    float4 a = ((const float4*)(g_Ybuf + (size_t)s0 * D_DIM))[d4];
    float4 b = ((const float4*)(g_Ybuf + (size_t)s1 * D_DIM))[d4];
    float4 o;
    o.x = w0 * a.x + w1 * b.x;
    o.y = w0 * a.y + w1 * b.y;
    o.z = w0 * a.z + w1 * b.z;
    o.w = w0 * a.w + w1 * b.w;
    ((float4*)(out + (size_t)t * D_DIM))[d4] = o;
}

// ------------------------------- launch ------------------------------------
extern "C" void kernel_launch(void* const* d_in, const int* in_sizes, int n_in,
                              void* d_out, int out_size)
{
    const float* x  = (const float*)d_in[0];
    const float* Wg = (const float*)d_in[1];
    const float* W1 = (const float*)d_in[2];
    const float* b1 = (const float*)d_in[3];
    const float* W2 = (const float*)d_in[4];
    const float* b2 = (const float*)d_in[5];
    float* out = (float*)d_out;

    int T = in_sizes[0] / D_DIM;
    if (T > MAXT) T = MAXT;

    int nblk = (T + 7) / 8;
    router_kernel<<<nblk, 256>>>(x, Wg, T);
    reduce_kernel<<<1, 32>>>(nblk, T, out + (size_t)T * D_DIM);
    scatter_kernel<<<(T + 255) / 256, 256>>>(T);

    int rowTilesMax = (T + 127) / 128;   // worst case: one expert takes all
    // colTile-fastest grid: concurrent CTAs share A/H rows; W stays in L2
    moe_gemm_mma<D_DIM, H_DIM, true ><<<dim3(H_DIM / 128, rowTilesMax, NE), 256>>>(x, W1, b1);
    moe_gemm_mma<H_DIM, D_DIM, false><<<dim3(D_DIM / 128, rowTilesMax, NE), 256>>>(nullptr, W2, b2);

    combine_kernel<<<(unsigned)(((size_t)T * 256 + 255) / 256), 256>>>(out, T);
}

// round 13
// speedup vs baseline: 2.5899x; 1.0073x over previous
#include <cuda_runtime.h>
#include <cuda_bf16.h>
#include <cstdint>
#include <math.h>

// ---------------------------------------------------------------------------
// MoE: B=4,S=2048,D=1024,H=4096,E=8,top2. T=8192.
// HMMA bf16 split GEMMs (Ah*Bh + Ah*Bl + Al*Bh), in-kernel fp32->bf16 split.
// R13: term-major MMA order (dependent-chain distance 1 -> 4), incremental
// global pointers. CTA 128x128, BK=16, warp 64x32 (2Mx4N), 2x16KB smem.
// Envelope: static smem <= 48KB, no cudaFuncSetAttribute, no cp.async,
// no lambdas, globals ~320MB.
// ---------------------------------------------------------------------------

#define D_DIM 1024
#define H_DIM 4096
#define NE    8
#define MAXT  8192
#define MAXSLOT (MAXT * 2)
#define MAXRBLK (MAXT / 8)

__device__ float g_partp[MAXRBLK * NE];
__device__ int   g_partc[MAXRBLK * NE];
__device__ float g_psum[NE];
__device__ int   g_cnt[NE];
__device__ int   g_off[NE + 1];
__device__ int   g_cur[NE];
__device__ int   g_idx2[MAXT * 2];
__device__ float g_w2[MAXT * 2];
__device__ int   g_slot[MAXT * 2];
__device__ int   g_tok[MAXSLOT];
__device__ float g_Hbuf[(size_t)MAXSLOT * H_DIM];  // 256 MB fp32
__device__ float g_Ybuf[(size_t)MAXSLOT * D_DIM];  // 64 MB fp32

// ------------------------------- helpers -----------------------------------
__device__ __forceinline__ uint32_t smem_u32(const void* p) {
    uint32_t a;
    asm("{ .reg .u64 t; cvta.to.shared.u64 t, %1; cvt.u32.u64 %0, t; }"
        : "=r"(a) : "l"(p));
    return a;
}
__device__ __forceinline__ void ldm_x4(uint32_t& r0, uint32_t& r1,
                                       uint32_t& r2, uint32_t& r3, uint32_t addr) {
    asm volatile("ldmatrix.sync.aligned.m8n8.x4.shared.b16 {%0,%1,%2,%3}, [%4];\n"
                 : "=r"(r0), "=r"(r1), "=r"(r2), "=r"(r3) : "r"(addr));
}
__device__ __forceinline__ void ldm_x4_t(uint32_t& r0, uint32_t& r1,
                                         uint32_t& r2, uint32_t& r3, uint32_t addr) {
    asm volatile("ldmatrix.sync.aligned.m8n8.x4.trans.shared.b16 {%0,%1,%2,%3}, [%4];\n"
                 : "=r"(r0), "=r"(r1), "=r"(r2), "=r"(r3) : "r"(addr));
}
__device__ __forceinline__ void mma16816(float& d0, float& d1, float& d2, float& d3,
                                         uint32_t a0, uint32_t a1, uint32_t a2, uint32_t a3,
                                         uint32_t b0, uint32_t b1) {
    asm volatile(
        "mma.sync.aligned.m16n8k16.row.col.f32.bf16.bf16.f32 "
        "{%0,%1,%2,%3}, {%4,%5,%6,%7}, {%8,%9}, {%0,%1,%2,%3};\n"
        : "+f"(d0), "+f"(d1), "+f"(d2), "+f"(d3)
        : "r"(a0), "r"(a1), "r"(a2), "r"(a3), "r"(b0), "r"(b1));
}
__device__ __forceinline__ void sts16(uint32_t addr, uint32_t x, uint32_t y,
                                      uint32_t z, uint32_t w) {
    asm volatile("st.shared.v4.b32 [%0], {%1,%2,%3,%4};\n"
                 :: "r"(addr), "r"(x), "r"(y), "r"(z), "r"(w) : "memory");
}
// A tile (BK=16): 128 rows x 16 bf16 = 32B/row, packed 2 rows per 64B line.
// sub = (row&1)*2 + c, phys = sub ^ ((row>>2)&1). Conflict-free both paths.
__device__ __forceinline__ uint32_t a16_off(int row, int c) {
    int sub = (row & 1) * 2 + c;
    return (uint32_t)(((row >> 1) * 4 + (sub ^ ((row >> 2) & 1))) << 4);
}
// B tile (BK=16): 16 k-rows x 128 bf16 = 256B/row, 16 chunks, swizzle c^(k&7).
__device__ __forceinline__ uint32_t b16_off(int k, int c) {
    return (uint32_t)((k * 16 + (c ^ (k & 7))) << 4);
}
// fast split: 2 floats -> bf16x2 hi + bf16x2 lo (6 ops)
__device__ __forceinline__ void split2(float v0, float v1, uint32_t& h, uint32_t& l) {
    uint32_t hv, h0b, h1b;
    asm("cvt.rn.bf16x2.f32 %0, %1, %2;" : "=r"(hv) : "f"(v1), "f"(v0));
    asm("prmt.b32 %0, %1, 0, 0x1044;" : "=r"(h0b) : "r"(hv));   // h0 << 16
    asm("prmt.b32 %0, %1, 0, 0x3244;" : "=r"(h1b) : "r"(hv));   // h1 << 16
    float l0 = v0 - __uint_as_float(h0b);
    float l1 = v1 - __uint_as_float(h1b);
    asm("cvt.rn.bf16x2.f32 %0, %1, %2;" : "=r"(l) : "f"(l1), "f"(l0));
    h = hv;
}
__device__ __forceinline__ float gelu_f(float v) {
    return 0.5f * v * (1.0f + erff(v * 0.7071067811865476f));
}

// ------------------------------- router ------------------------------------
__global__ __launch_bounds__(256) void router_kernel(
    const float* __restrict__ x, const float* __restrict__ Wg, int T)
{
    __shared__ float sp[8][NE];
    __shared__ int   si[8][2];
    int tid = threadIdx.x, warp = tid >> 5, lane = tid & 31;
    int t = blockIdx.x * 8 + warp;

    float acc[NE];
#pragma unroll
    for (int e = 0; e < NE; e++) acc[e] = 0.f;
    if (t < T) {
        const float* xr = x + (size_t)t * D_DIM;
        for (int d = lane; d < D_DIM; d += 32) {
            float xv = xr[d];
            const float* wr = Wg + d * NE;
#pragma unroll
            for (int e = 0; e < NE; e++) acc[e] += xv * wr[e];
        }
    }
#pragma unroll
    for (int e = 0; e < NE; e++)
#pragma unroll
        for (int o = 16; o > 0; o >>= 1)
            acc[e] += __shfl_xor_sync(0xFFFFFFFFu, acc[e], o);

    if (lane == 0) {
        if (t < T) {
            float m = acc[0];
#pragma unroll
            for (int e = 1; e < NE; e++) m = fmaxf(m, acc[e]);
            float p[NE]; float s = 0.f;
#pragma unroll
            for (int e = 0; e < NE; e++) { p[e] = expf(acc[e] - m); s += p[e]; }
            float inv = 1.0f / s;
#pragma unroll
            for (int e = 0; e < NE; e++) p[e] *= inv;
            int i0 = 0; float v0 = p[0];
#pragma unroll
            for (int e = 1; e < NE; e++)
                if (p[e] > v0) { v0 = p[e]; i0 = e; }
            int i1 = -1; float v1 = -1.f;
#pragma unroll
            for (int e = 0; e < NE; e++) {
                if (e == i0) continue;
                if (p[e] > v1) { v1 = p[e]; i1 = e; }
            }
            float ws = v0 + v1;
            g_idx2[2 * t] = i0;  g_idx2[2 * t + 1] = i1;
            g_w2[2 * t] = v0 / ws;  g_w2[2 * t + 1] = v1 / ws;
#pragma unroll
            for (int e = 0; e < NE; e++) sp[warp][e] = p[e];
            si[warp][0] = i0; si[warp][1] = i1;
        } else {
#pragma unroll
            for (int e = 0; e < NE; e++) sp[warp][e] = 0.f;
            si[warp][0] = -1; si[warp][1] = -1;
        }
    }
    __syncthreads();
    if (tid < NE) {
        float s = 0.f; int c = 0;
#pragma unroll
        for (int w = 0; w < 8; w++) {
            s += sp[w][tid];
            if (si[w][0] == tid || si[w][1] == tid) c++;
        }
        g_partp[blockIdx.x * NE + tid] = s;
        g_partc[blockIdx.x * NE + tid] = c;
    }
}

__global__ void reduce_kernel(int nblk, int T, float* __restrict__ aux_out) {
    int tid = threadIdx.x;
    if (tid < NE) {
        float ps = 0.f; int cs = 0;
        for (int b = 0; b < nblk; b++) {
            ps += g_partp[b * NE + tid];
            cs += g_partc[b * NE + tid];
        }
        g_psum[tid] = ps; g_cnt[tid] = cs; g_cur[tid] = 0;
    }
    __syncthreads();
    if (tid == 0) {
        int off = 0;
        for (int e = 0; e < NE; e++) { g_off[e] = off; off += g_cnt[e]; }
        g_off[NE] = off;
        float invT = 1.0f / (float)T;
        float aux = 0.f;
        for (int e = 0; e < NE; e++)
            aux += ((float)g_cnt[e] * invT) * (g_psum[e] * invT);
        *aux_out = (float)NE * aux;
    }
}

__global__ void scatter_kernel(int T) {
    int t = blockIdx.x * 256 + threadIdx.x;
    if (t >= T) return;
#pragma unroll
    for (int k = 0; k < 2; k++) {
        int e = g_idx2[2 * t + k];
        int pos = atomicAdd(&g_cur[e], 1);
        int s = g_off[e] + pos;
        g_tok[s] = t;
        g_slot[2 * t + k] = s;
    }
}

// --------------------------- HMMA grouped GEMM -----------------------------
// CTA 128(M) x 128(N), BK=16. 8 warps (2Mx4N), warp tile 64x32.
// Double-buffered smem 2 x 16KB; per stage: Ah 4K | Al 4K | Bh 4K | Bl 4K.
// iter s: STORES(stage s+1 -> other buf); LOADG(stage s+2); MMA(stage s); bar.
#define BUF_BYTES 16384

#define LOADG() do {                                                          \
    ra0 = *(const float4*)(pA);                                               \
    ra1 = *(const float4*)(pA + 4);                                           \
    rb0 = *(const float4*)(pB);                                               \
    rb1 = *(const float4*)(pB + 4);                                           \
    pA += 16;  pB += (size_t)16 * NTOT;                                       \
} while (0)

#define STORES(BB) do {                                                       \
    uint32_t h0_,h1_,h2_,h3_, l0_,l1_,l2_,l3_;                                \
    split2(ra0.x, ra0.y, h0_, l0_);  split2(ra0.z, ra0.w, h1_, l1_);          \
    split2(ra1.x, ra1.y, h2_, l2_);  split2(ra1.z, ra1.w, h3_, l3_);          \
    sts16((BB) + sAo, h0_, h1_, h2_, h3_);                                    \
    sts16((BB) + 4096 + sAo, l0_, l1_, l2_, l3_);                             \
    split2(rb0.x, rb0.y, h0_, l0_);  split2(rb0.z, rb0.w, h1_, l1_);          \
    split2(rb1.x, rb1.y, h2_, l2_);  split2(rb1.z, rb1.w, h3_, l3_);          \
    sts16((BB) + 8192 + sBo, h0_, h1_, h2_, h3_);                             \
    sts16((BB) + 12288 + sBo, l0_, l1_, l2_, l3_);                            \
} while (0)

// Term-major MMA order: per m-tile I, term-h over j0..3, term-bl over j0..3,
// term-al over j0..3. Dependent reuse distance = 4 (was 1). Accumulation
// order into each acc[I][j] unchanged (h, bl, al) -> bitwise-identical.
#define MMAROW(I)                                                                             \
    mma16816(acc[I][0][0],acc[I][0][1],acc[I][0][2],acc[I][0][3], a0,a1,a2,a3, u0,u1);        \
    mma16816(acc[I][1][0],acc[I][1][1],acc[I][1][2],acc[I][1][3], a0,a1,a2,a3, u2,u3);        \
    mma16816(acc[I][2][0],acc[I][2][1],acc[I][2][2],acc[I][2][3], a0,a1,a2,a3, u4,u5);        \
    mma16816(acc[I][3][0],acc[I][3][1],acc[I][3][2],acc[I][3][3], a0,a1,a2,a3, u6,u7);        \
    mma16816(acc[I][0][0],acc[I][0][1],acc[I][0][2],acc[I][0][3], a0,a1,a2,a3, w0,w1);        \
    mma16816(acc[I][1][0],acc[I][1][1],acc[I][1][2],acc[I][1][3], a0,a1,a2,a3, w2,w3);        \
    mma16816(acc[I][2][0],acc[I][2][1],acc[I][2][2],acc[I][2][3], a0,a1,a2,a3, w4,w5);        \
    mma16816(acc[I][3][0],acc[I][3][1],acc[I][3][2],acc[I][3][3], a0,a1,a2,a3, w6,w7);        \
    mma16816(acc[I][0][0],acc[I][0][1],acc[I][0][2],acc[I][0][3], c0,c1,c2,c3, u0,u1);        \
    mma16816(acc[I][1][0],acc[I][1][1],acc[I][1][2],acc[I][1][3], c0,c1,c2,c3, u2,u3);        \
    mma16816(acc[I][2][0],acc[I][2][1],acc[I][2][2],acc[I][2][3], c0,c1,c2,c3, u4,u5);        \
    mma16816(acc[I][3][0],acc[I][3][1],acc[I][3][2],acc[I][3][3], c0,c1,c2,c3, u6,u7);

#define KSTEP16(BB) do {                                                      \
    uint32_t u0,u1,u2,u3,u4,u5,u6,u7, w0,w1,w2,w3,w4,w5,w6,w7;                \
    ldm_x4_t(u0,u1,u2,u3, (BB) + 8192 + offB0);                               \
    ldm_x4_t(u4,u5,u6,u7, (BB) + 8192 + offB1);                               \
    ldm_x4_t(w0,w1,w2,w3, (BB) + 12288 + offB0);                              \
    ldm_x4_t(w4,w5,w6,w7, (BB) + 12288 + offB1);                              \
    {   uint32_t a0,a1,a2,a3, c0,c1,c2,c3;                                    \
        ldm_x4(a0,a1,a2,a3, (BB) + offA0);                                    \
        ldm_x4(c0,c1,c2,c3, (BB) + 4096 + offA0);                             \
        MMAROW(0)                                                             \
    }                                                                         \
    {   uint32_t a0,a1,a2,a3, c0,c1,c2,c3;                                    \
        ldm_x4(a0,a1,a2,a3, (BB) + offA1);                                    \
        ldm_x4(c0,c1,c2,c3, (BB) + 4096 + offA1);                             \
        MMAROW(1)                                                             \
    }                                                                         \
    {   uint32_t a0,a1,a2,a3, c0,c1,c2,c3;                                    \
        ldm_x4(a0,a1,a2,a3, (BB) + offA2);                                    \
        ldm_x4(c0,c1,c2,c3, (BB) + 4096 + offA2);                             \
        MMAROW(2)                                                             \
    }                                                                         \
    {   uint32_t a0,a1,a2,a3, c0,c1,c2,c3;                                    \
        ldm_x4(a0,a1,a2,a3, (BB) + offA3);                                    \
        ldm_x4(c0,c1,c2,c3, (BB) + 4096 + offA3);                             \
        MMAROW(3)                                                             \
    }                                                                         \
} while (0)

template <int KDIM, int NTOT, bool FIRST>
__global__ __launch_bounds__(256, 2) void moe_gemm_mma(
    const float* __restrict__ xsrc,      // x for FIRST (else unused)
    const float* __restrict__ W,         // [E][KDIM][NTOT] fp32
    const float* __restrict__ bias)      // [E][NTOT] fp32
{
    constexpr int NS = KDIM / 16;
    int e = blockIdx.z;
    int seg0 = g_off[e];
    int M = g_off[e + 1] - seg0;
    int rowTile = blockIdx.y * 128;       // colTile-fastest grid (L2 reuse)
    if (rowTile >= M) return;
    int colTile = blockIdx.x * 128;

    __shared__ __align__(128) char sbuf[2][BUF_BYTES];   // 32 KB

    int tid = threadIdx.x, wid = tid >> 5, lane = tid & 31;
    const float* srcA = FIRST ? xsrc : g_Hbuf;

    // ---- per-thread loader constants ----
    int arow = tid >> 1, ac = tid & 1;
    int rA_g = rowTile + arow;
    int groff;
    if (FIRST) {
        groff = ((rA_g < M) ? g_tok[seg0 + rA_g] : g_tok[seg0]) * KDIM;
    } else {
        groff = (seg0 + ((rA_g < M) ? rA_g : 0)) * KDIM;
    }
    const float* pA = srcA + groff + ac * 8;
    uint32_t sAo = a16_off(arow, ac);
    int bk = tid >> 4, bc = tid & 15;
    const float* pB = W + ((size_t)e * KDIM + bk) * NTOT + colTile + bc * 8;
    uint32_t sBo = b16_off(bk, bc);

    // ---- ldmatrix offsets ----
    int warpM = (wid & 1) * 64;
    int warpN = (wid >> 1) * 32;
    int lrow = lane & 15, lch = lane >> 4;
    uint32_t offA0 = a16_off(warpM + 0  + lrow, lch);
    uint32_t offA1 = a16_off(warpM + 16 + lrow, lch);
    uint32_t offA2 = a16_off(warpM + 32 + lrow, lch);
    uint32_t offA3 = a16_off(warpM + 48 + lrow, lch);
    int nb = warpN >> 3;
    uint32_t offB0 = b16_off(lane & 15, nb + (lane >> 4));
    uint32_t offB1 = b16_off(lane & 15, nb + 2 + (lane >> 4));

    float acc[4][4][4];
#pragma unroll
    for (int i = 0; i < 4; i++)
#pragma unroll
        for (int j = 0; j < 4; j++)
#pragma unroll
            for (int q = 0; q < 4; q++) acc[i][j][q] = 0.f;

    uint32_t sb0 = smem_u32(sbuf);
    float4 ra0, ra1, rb0, rb1;

    // prologue
    LOADG();
    STORES(sb0);
    LOADG();
    __syncthreads();

    for (int s = 0; s < NS; s++) {
        uint32_t cur = sb0 + (uint32_t)(s & 1) * BUF_BYTES;
        uint32_t nxt = sb0 + (uint32_t)((s + 1) & 1) * BUF_BYTES;
        if (s + 1 < NS) STORES(nxt);
        if (s + 2 < NS) LOADG();
        KSTEP16(cur);
        __syncthreads();
    }

    // ----- epilogue -----
    const float* bcolBase = bias + (size_t)e * NTOT + colTile;
#pragma unroll
    for (int i = 0; i < 4; i++) {
        int r0e = warpM + i * 16 + (lane >> 2);
#pragma unroll
        for (int h = 0; h < 2; h++) {
            int grow = rowTile + r0e + h * 8;
            if (grow >= M) continue;
            size_t orow = (size_t)(seg0 + grow) * NTOT + colTile;
#pragma unroll
            for (int j = 0; j < 4; j++) {
                int col = warpN + j * 8 + (lane & 3) * 2;
                float v0 = acc[i][j][2 * h]     + bcolBase[col];
                float v1 = acc[i][j][2 * h + 1] + bcolBase[col + 1];
                if (FIRST) {
                    v0 = gelu_f(v0); v1 = gelu_f(v1);
                    *(float2*)(g_Hbuf + orow + col) = make_float2(v0, v1);
                } else {
                    *(float2*)(g_Ybuf + orow + col) = make_float2(v0, v1);
                }
            }
        }
    }
}

// ------------------------------- combine -----------------------------------
__global__ __launch_bounds__(256) void combine_kernel(float* __restrict__ out, int T) {
    size_t i = (size_t)blockIdx.x * 256 + threadIdx.x;
    size_t total = (size_t)T * (D_DIM / 4);
    if (i >= total) return;
    int t  = (int)(i >> 8);
    int d4 = (int)(i & 255);
    float w0 = g_w2[2 * t], w1 = g_w2[2 * t + 1];
    int s0 = g_slot[2 * t], s1 = g_slot[2 * t + 1];
    float4 a = ((const float4*)(g_Ybuf + (size_t)s0 * D_DIM))[d4];
    float4 b = ((const float4*)(g_Ybuf + (size_t)s1 * D_DIM))[d4];
    float4 o;
    o.x = w0 * a.x + w1 * b.x;
    o.y = w0 * a.y + w1 * b.y;
    o.z = w0 * a.z + w1 * b.z;
    o.w = w0 * a.w + w1 * b.w;
    ((float4*)(out + (size_t)t * D_DIM))[d4] = o;
}

// ------------------------------- launch ------------------------------------
extern "C" void kernel_launch(void* const* d_in, const int* in_sizes, int n_in,
                              void* d_out, int out_size)
{
    const float* x  = (const float*)d_in[0];
    const float* Wg = (const float*)d_in[1];
    const float* W1 = (const float*)d_in[2];
    const float* b1 = (const float*)d_in[3];
    const float* W2 = (const float*)d_in[4];
    const float* b2 = (const float*)d_in[5];
    float* out = (float*)d_out;

    int T = in_sizes[0] / D_DIM;
    if (T > MAXT) T = MAXT;

    int nblk = (T + 7) / 8;
    router_kernel<<<nblk, 256>>>(x, Wg, T);
    reduce_kernel<<<1, 32>>>(nblk, T, out + (size_t)T * D_DIM);
    scatter_kernel<<<(T + 255) / 256, 256>>>(T);

    int rowTilesMax = (T + 127) / 128;   // worst case: one expert takes all
    // colTile-fastest grid: concurrent CTAs share A/H rows; W stays in L2
    moe_gemm_mma<D_DIM, H_DIM, true ><<<dim3(H_DIM / 128, rowTilesMax, NE), 256>>>(x, W1, b1);
    moe_gemm_mma<H_DIM, D_DIM, false><<<dim3(D_DIM / 128, rowTilesMax, NE), 256>>>(nullptr, W2, b2);

    combine_kernel<<<(unsigned)(((size_t)T * 256 + 255) / 256), 256>>>(out, T);
}